// round 8
// baseline (speedup 1.0000x reference)
#include <cuda_runtime.h>
#include <cuda_bf16.h>
#include <math.h>
#include <stdint.h>

// ---------------- dims ----------------
#define NPTS 131072
#define PTS  64             // points per block
#define TPB  128            // 4 warps, each owns 16 points x full N=128
#define NBLK (NPTS/PTS)     // 2048
#define HID  128
#define L1_KT 13            // K = 208 (194 real + bias row + pad)
#define L23_KT 8            // K = 128
#define TOT_KT 29           // 13 + 8 + 8, contiguous slabs in g_wfrag

// ---------------- smem layout (bytes) ----------------
#define SA_STRIDE 432       // feature row stride: 216 bf16 (16B-aligned)
#define SA_HALF   27648     // 64*432, lo buffer offset
#define SM_B2 0             // b2: 128 f32
#define SM_B3 512           // b3: 128 f32
#define SM_BB 1024          // B double buffer: 2 x 8192
#define SM_A  17408
#define SM_TOTAL (SM_A + 2*SA_HALF)   // 72704 -> 3 blocks/SM (213KB)

// weight fragment array (uint4 units): contiguous kt-slabs L1|L2|L3, 512 per kt
#define WF_TOTAL (TOT_KT*512)

// ---------------- device scratch ----------------
__device__ float g_zt[16*64*64*64];          // z transposed (B,H,W,C)
__device__ uint4 g_wfrag[WF_TOTAL];          // MMA b-fragments {b0h,b1h,b0l,b1l}
__device__ float g_wh[HID*8];                // head weights [k][o]
__device__ float g_hb[8];                    // head biases

// ---------------- helpers ----------------
__device__ __forceinline__ uint32_t smem_u32(const void* p) {
    uint32_t a;
    asm("{ .reg .u64 t; cvta.to.shared.u64 t, %1; cvt.u32.u64 %0, t; }" : "=r"(a) : "l"(p));
    return a;
}
__device__ __forceinline__ void ldsm4(uint32_t* r, uint32_t a) {
    asm volatile("ldmatrix.sync.aligned.m8n8.x4.shared.b16 {%0,%1,%2,%3}, [%4];"
                 : "=r"(r[0]), "=r"(r[1]), "=r"(r[2]), "=r"(r[3]) : "r"(a));
}
__device__ __forceinline__ uint4 lds128(uint32_t a) {
    uint4 v;
    asm volatile("ld.shared.v4.b32 {%0,%1,%2,%3}, [%4];"
                 : "=r"(v.x), "=r"(v.y), "=r"(v.z), "=r"(v.w) : "r"(a));
    return v;
}
__device__ __forceinline__ void cpasync16(uint32_t dst, const void* src) {
    asm volatile("cp.async.cg.shared.global [%0], [%1], 16;" :: "r"(dst), "l"(src) : "memory");
}
#define CP_COMMIT() asm volatile("cp.async.commit_group;" ::: "memory")
#define CP_WAIT0()  asm volatile("cp.async.wait_group 0;" ::: "memory")

__device__ __forceinline__ void mma_bf16(float* d, const uint32_t* a, uint32_t b0, uint32_t b1) {
    asm volatile("mma.sync.aligned.m16n8k16.row.col.f32.bf16.bf16.f32 "
                 "{%0,%1,%2,%3}, {%4,%5,%6,%7}, {%8,%9}, {%0,%1,%2,%3};"
                 : "+f"(d[0]), "+f"(d[1]), "+f"(d[2]), "+f"(d[3])
                 : "r"(a[0]), "r"(a[1]), "r"(a[2]), "r"(a[3]), "r"(b0), "r"(b1));
}
// fast tanh: 1 - 2/(exp(2x)+1); ~1e-6 abs err
__device__ __forceinline__ float ftanh(float x) {
    float e = __expf(2.f * x);
    float r;
    asm("rcp.approx.f32 %0, %1;" : "=f"(r) : "f"(e + 1.f));
    return fmaf(-2.f, r, 1.f);
}
// pack (a,b) fp32 pair -> hi bf16x2 word + lo (residual) bf16x2 word
__device__ __forceinline__ void split2(float a, float b, uint32_t& hi, uint32_t& lo) {
    __nv_bfloat16 ah = __float2bfloat16(a), bh = __float2bfloat16(b);
    __nv_bfloat16 al = __float2bfloat16(a - __bfloat162float(ah));
    __nv_bfloat16 bl = __float2bfloat16(b - __bfloat162float(bh));
    hi = (uint32_t)__bfloat16_as_ushort(ah) | ((uint32_t)__bfloat16_as_ushort(bh) << 16);
    lo = (uint32_t)__bfloat16_as_ushort(al) | ((uint32_t)__bfloat16_as_ushort(bl) << 16);
}
// fast sin/cos with explicit 2-step 2*pi range reduction
__device__ __forceinline__ void fsincos(float x, float& s, float& c) {
    float k = rintf(x * 0.15915494309189535f);
    float r = fmaf(-k, 6.2831855f, x);
    r = fmaf(-k, -1.7484555e-7f, r);
    s = __sinf(r);
    c = __cosf(r);
}

// ---------------- prologue kernels ----------------
__global__ void __launch_bounds__(256) transpose_z_kernel(const float* __restrict__ z) {
    int i = blockIdx.x * 256 + threadIdx.x;
    int x = i & 63, y = (i >> 6) & 63, c = (i >> 12) & 63, b = i >> 18;
    g_zt[(((((b << 6) + y) << 6) + x) << 6) + c] = z[i];
}

// Pre-pack weights into MMA col-major b-fragment layout, contiguous kt-slabs.
// slab s: s<13 -> W1 kt=s; s<21 -> W2 kt=s-13; else W3 kt=s-21
__global__ void __launch_bounds__(256) prep_wfrag_kernel(
    const float* __restrict__ W1, const float* __restrict__ b1,
    const float* __restrict__ W2, const float* __restrict__ W3)
{
    int i = blockIdx.x * 256 + threadIdx.x;
    if (i >= WF_TOTAL) return;
    int s = i >> 9, rem = i & 511;
    int lane = rem & 31, nt = rem >> 5;
    int layer, kt;
    const float* W;
    if (s < 13)      { layer = 1; kt = s;      W = W1; }
    else if (s < 21) { layer = 2; kt = s - 13; W = W2; }
    else             { layer = 3; kt = s - 21; W = W3; }
    int n  = nt * 8 + (lane >> 2);
    int k0 = kt * 16 + (lane & 3) * 2;
    float v[4];
    #pragma unroll
    for (int j = 0; j < 4; j++) {
        int k = k0 + (j >> 1) * 8 + (j & 1);
        float val;
        if (layer == 1) {
            if (k < 194)       val = W[k * HID + n];
            else if (k == 194) val = b1[n];
            else               val = 0.f;
        } else {
            val = W[k * HID + n];
        }
        v[j] = val;
    }
    uint4 o;
    split2(v[0], v[1], o.x, o.z);
    split2(v[2], v[3], o.y, o.w);
    g_wfrag[i] = o;
}

__global__ void __launch_bounds__(128) prep_heads_kernel(
    const float* __restrict__ Wvel, const float* __restrict__ bvel,
    const float* __restrict__ Wfh,  const float* __restrict__ bfh,
    const float* __restrict__ Wph,  const float* __restrict__ bph,
    const float* __restrict__ Wmu,  const float* __restrict__ bmu,
    const float* __restrict__ Wstd, const float* __restrict__ bstd)
{
    int k = threadIdx.x;
    g_wh[k * 8 + 0] = Wvel[k * 2 + 0];
    g_wh[k * 8 + 1] = Wvel[k * 2 + 1];
    g_wh[k * 8 + 2] = Wfh[k * 2 + 0];
    g_wh[k * 8 + 3] = Wfh[k * 2 + 1];
    g_wh[k * 8 + 4] = Wph[k * 2 + 0];
    g_wh[k * 8 + 5] = Wph[k * 2 + 1];
    g_wh[k * 8 + 6] = Wmu[k];
    g_wh[k * 8 + 7] = Wstd[k];
    if (k < 8) {
        float hb;
        if      (k < 2)  hb = bvel[k];
        else if (k < 4)  hb = bfh[k - 2];
        else if (k < 6)  hb = bph[k - 4];
        else if (k == 6) hb = bmu[0];
        else             hb = bstd[0];
        g_hb[k] = hb;
    }
}

// interleaved group of 4 n-tiles reading staged B from smem
__device__ __forceinline__ void mma_group4s(float (*d)[4], const uint32_t* Ah, const uint32_t* Al,
                                            uint32_t bAddr, int ntBase) {
    uint4 B0 = lds128(bAddr + (ntBase + 0) * 512);
    uint4 B1 = lds128(bAddr + (ntBase + 1) * 512);
    uint4 B2 = lds128(bAddr + (ntBase + 2) * 512);
    uint4 B3 = lds128(bAddr + (ntBase + 3) * 512);
    float* d0 = d[ntBase + 0];
    float* d1 = d[ntBase + 1];
    float* d2 = d[ntBase + 2];
    float* d3 = d[ntBase + 3];
    mma_bf16(d0, Ah, B0.x, B0.y);
    mma_bf16(d1, Ah, B1.x, B1.y);
    mma_bf16(d2, Ah, B2.x, B2.y);
    mma_bf16(d3, Ah, B3.x, B3.y);
    mma_bf16(d0, Al, B0.x, B0.y);
    mma_bf16(d1, Al, B1.x, B1.y);
    mma_bf16(d2, Al, B2.x, B2.y);
    mma_bf16(d3, Al, B3.x, B3.y);
    mma_bf16(d0, Ah, B0.z, B0.w);
    mma_bf16(d1, Ah, B1.z, B1.w);
    mma_bf16(d2, Ah, B2.z, B2.w);
    mma_bf16(d3, Ah, B3.z, B3.w);
}

// ---------------- main kernel ----------------
__global__ void __launch_bounds__(TPB, 3) pinn_main(
    const float* __restrict__ coords, const float* __restrict__ fourierB,
    const float* __restrict__ b2g, const float* __restrict__ b3g,
    float* __restrict__ out)
{
    extern __shared__ __align__(16) unsigned char smem[];
    const uint32_t sb = smem_u32(smem);
    const int tid  = threadIdx.x;
    const int lane = tid & 31;
    const int warp = tid >> 5;        // 0..3, owns rows warp*16..warp*16+15

    // ---- kick slab 0 staging immediately (overlaps feature build) ----
    {
        const uint4* src = g_wfrag + tid;
        uint32_t dst = sb + SM_BB + tid * 16;
        #pragma unroll
        for (int j = 0; j < 4; j++)
            cpasync16(dst + j * 2048, src + j * 128);
        CP_COMMIT();
    }

    float* sb2 = (float*)(smem + SM_B2);
    float* sb3 = (float*)(smem + SM_B3);
    sb2[tid] = b2g[tid];
    sb3[tid] = b3g[tid];

    // ---- feature build: 2 threads per point (64 points) ----
    {
        int p = tid >> 1, role = tid & 1;
        int m = blockIdx.x * PTS + p;
        uint32_t rowOff = SM_A + (uint32_t)p * SA_STRIDE;
        if (role == 0) {
            float cx = coords[m * 3 + 0], cy = coords[m * 3 + 1];
            int b = m >> 13;
            float fx = (cx + 1.f) * 0.5f * 63.f;
            float fy = (cy + 1.f) * 0.5f * 63.f;
            float x0f = floorf(fx), y0f = floorf(fy);
            int x0 = min(max((int)x0f, 0), 63);
            int x1 = max(min((int)x0f + 1, 63), 0);
            int y0 = min(max((int)y0f, 0), 63);
            int y1 = max(min((int)y0f + 1, 63), 0);
            float wa = (x0f + 1.f - fx) * (y0f + 1.f - fy);
            float wb = (x0f + 1.f - fx) * (fy - y0f);
            float wc = (fx - x0f) * (y0f + 1.f - fy);
            float wd = (fx - x0f) * (fy - y0f);
            const float4* p00 = (const float4*)(g_zt + ((((b << 6) + y0) << 6) + x0) * 64);
            const float4* p01 = (const float4*)(g_zt + ((((b << 6) + y1) << 6) + x0) * 64);
            const float4* p10 = (const float4*)(g_zt + ((((b << 6) + y0) << 6) + x1) * 64);
            const float4* p11 = (const float4*)(g_zt + ((((b << 6) + y1) << 6) + x1) * 64);
            #pragma unroll
            for (int g = 0; g < 16; g++) {
                float4 A = p00[g], B = p01[g], C = p10[g], D = p11[g];
                float v0 = wa*A.x + wb*B.x + wc*C.x + wd*D.x;
                float v1 = wa*A.y + wb*B.y + wc*C.y + wd*D.y;
                float v2 = wa*A.z + wb*B.z + wc*C.z + wd*D.z;
                float v3 = wa*A.w + wb*B.w + wc*C.w + wd*D.w;
                uint32_t h0, l0, h1, l1;
                split2(v0, v1, h0, l0);
                split2(v2, v3, h1, l1);
                *(uint32_t*)(smem + rowOff + g * 8)               = h0;
                *(uint32_t*)(smem + rowOff + g * 8 + 4)           = h1;
                *(uint32_t*)(smem + rowOff + SA_HALF + g * 8)     = l0;
                *(uint32_t*)(smem + rowOff + SA_HALF + g * 8 + 4) = l1;
            }
            // tail: cols 192..207 -> (cx,cy), (1,0), zeros
            uint32_t h, l;
            split2(cx, cy, h, l);
            *(uint32_t*)(smem + rowOff + 384)           = h;
            *(uint32_t*)(smem + rowOff + SA_HALF + 384) = l;
            split2(1.f, 0.f, h, l);
            *(uint32_t*)(smem + rowOff + 388)           = h;
            *(uint32_t*)(smem + rowOff + SA_HALF + 388) = l;
            #pragma unroll
            for (int w = 0; w < 6; w++) {
                *(uint32_t*)(smem + rowOff + 392 + w * 4)           = 0;
                *(uint32_t*)(smem + rowOff + SA_HALF + 392 + w * 4) = 0;
            }
        } else {
            float ct = coords[m * 3 + 2];
            const float tscale = 2.0943951023931953f * ct;  // 2*pi/TEMPORAL_MAX * t
            #pragma unroll 8
            for (int f = 0; f < 32; f++) {
                float s0, c0, s1, c1;
                fsincos(fourierB[2 * f]     * tscale, s0, c0);
                fsincos(fourierB[2 * f + 1] * tscale, s1, c1);
                uint32_t hs, ls, hc, lc;
                split2(s0, s1, hs, ls);
                split2(c0, c1, hc, lc);
                *(uint32_t*)(smem + rowOff + 128 + f * 4)           = hs;  // cols 64..127
                *(uint32_t*)(smem + rowOff + SA_HALF + 128 + f * 4) = ls;
                *(uint32_t*)(smem + rowOff + 256 + f * 4)           = hc;  // cols 128..191
                *(uint32_t*)(smem + rowOff + SA_HALF + 256 + f * 4) = lc;
            }
        }
    }
    __syncthreads();   // features + biases ready

    // ldmatrix A address for this warp's 16 rows
    const uint32_t aAddr = sb + SM_A + (uint32_t)(warp * 16 + (lane & 15)) * SA_STRIDE + (lane >> 4) * 16;

    float d[16][4];
    int s = 0;

    // ================= layer 1 (A from smem) =================
    #pragma unroll
    for (int nt = 0; nt < 16; nt++)
        #pragma unroll
        for (int i = 0; i < 4; i++) d[nt][i] = 0.f;
    #pragma unroll 1
    for (int kt = 0; kt < L1_KT; kt++, s++) {
        CP_WAIT0();
        __syncthreads();
        if (s + 1 < TOT_KT) {      // stage slab s+1 into the other buffer
            const uint4* src = g_wfrag + (s + 1) * 512 + tid;
            uint32_t dst = sb + SM_BB + ((s + 1) & 1) * 8192 + tid * 16;
            #pragma unroll
            for (int j = 0; j < 4; j++)
                cpasync16(dst + j * 2048, src + j * 128);
            CP_COMMIT();
        }
        uint32_t Ah[4], Al[4];
        ldsm4(Ah, aAddr + kt * 32);
        ldsm4(Al, aAddr + kt * 32 + SA_HALF);
        uint32_t bAddr = sb + SM_BB + (s & 1) * 8192 + lane * 16;
        #pragma unroll
        for (int ng = 0; ng < 4; ng++)
            mma_group4s(d, Ah, Al, bAddr, 4 * ng);
    }

    // epilogue 1 -> A2 in registers (bias folded into W1); D-frag == A-frag layout
    uint32_t A2h[8][4], A2l[8][4];
    #pragma unroll
    for (int kt = 0; kt < 8; kt++)
        #pragma unroll
        for (int j = 0; j < 4; j++) {
            int srcnt = 2 * kt + (j >> 1);
            int c = (j & 1) * 2;
            split2(ftanh(d[srcnt][c]), ftanh(d[srcnt][c + 1]), A2h[kt][j], A2l[kt][j]);
        }

    // ================= layer 2 (A in registers) =================
    #pragma unroll
    for (int nt = 0; nt < 16; nt++)
        #pragma unroll
        for (int i = 0; i < 4; i++) d[nt][i] = 0.f;
    #pragma unroll 1
    for (int kt = 0; kt < L23_KT; kt++, s++) {
        CP_WAIT0();
        __syncthreads();
        if (s + 1 < TOT_KT) {
            const uint4* src = g_wfrag + (s + 1) * 512 + tid;
            uint32_t dst = sb + SM_BB + ((s + 1) & 1) * 8192 + tid * 16;
            #pragma unroll
            for (int j = 0; j < 4; j++)
                cpasync16(dst + j * 2048, src + j * 128);
            CP_COMMIT();
        }
        uint32_t bAddr = sb + SM_BB + (s & 1) * 8192 + lane * 16;
        #pragma unroll
        for (int ng = 0; ng < 4; ng++)
            mma_group4s(d, A2h[kt], A2l[kt], bAddr, 4 * ng);
    }

    // epilogue 2: +b2, tanh -> A3 (reuse A2 arrays)
    #pragma unroll
    for (int kt = 0; kt < 8; kt++)
        #pragma unroll
        for (int j = 0; j < 4; j++) {
            int srcnt = 2 * kt + (j >> 1);
            int c = (j & 1) * 2;
            int col = 8 * srcnt + (lane & 3) * 2;
            float2 bb = *(float2*)(sb2 + col);
            split2(ftanh(d[srcnt][c] + bb.x), ftanh(d[srcnt][c + 1] + bb.y),
                   A2h[kt][j], A2l[kt][j]);
        }

    // ================= layer 3 (A in registers) =================
    #pragma unroll
    for (int nt = 0; nt < 16; nt++)
        #pragma unroll
        for (int i = 0; i < 4; i++) d[nt][i] = 0.f;
    #pragma unroll 1
    for (int kt = 0; kt < L23_KT; kt++, s++) {
        CP_WAIT0();
        __syncthreads();
        if (s + 1 < TOT_KT) {
            const uint4* src = g_wfrag + (s + 1) * 512 + tid;
            uint32_t dst = sb + SM_BB + ((s + 1) & 1) * 8192 + tid * 16;
            #pragma unroll
            for (int j = 0; j < 4; j++)
                cpasync16(dst + j * 2048, src + j * 128);
            CP_COMMIT();
        }
        uint32_t bAddr = sb + SM_BB + (s & 1) * 8192 + lane * 16;
        #pragma unroll
        for (int ng = 0; ng < 4; ng++)
            mma_group4s(d, A2h[kt], A2l[kt], bAddr, 4 * ng);
    }

    // epilogue 3: +b3, tanh -> fp32 feat in smem (stride 132 floats)
    {
        float* featF = (float*)(smem + SM_A);
        int row0 = warp * 16 + (lane >> 2);
        #pragma unroll
        for (int nt = 0; nt < 16; nt++) {
            int col = 8 * nt + (lane & 3) * 2;
            float2 bb = *(float2*)(sb3 + col);
            *(float2*)(featF + row0 * 132 + col) =
                make_float2(ftanh(d[nt][0] + bb.x), ftanh(d[nt][1] + bb.y));
            *(float2*)(featF + (row0 + 8) * 132 + col) =
                make_float2(ftanh(d[nt][2] + bb.x), ftanh(d[nt][3] + bb.y));
        }
    }
    __syncthreads();

    // ================= heads =================
    {
        const float* featF = (const float*)(smem + SM_A);
        int p = tid >> 1;
        int og = (tid & 1) * 4;
        const float4* wh4 = (const float4*)g_wh;
        float a0 = 0.f, a1 = 0.f, a2 = 0.f, a3 = 0.f;
        #pragma unroll 4
        for (int k = 0; k < HID; k++) {
            float f = featF[p * 132 + k];
            float4 w = __ldg(wh4 + k * 2 + (tid & 1));
            a0 += f * w.x; a1 += f * w.y; a2 += f * w.z; a3 += f * w.w;
        }
        a0 += g_hb[og]; a1 += g_hb[og + 1]; a2 += g_hb[og + 2]; a3 += g_hb[og + 3];
        if (og == 4) {  // output 7 = softplus(.) + MIN_STD
            a3 = fmaxf(a3, 0.f) + log1pf(expf(-fabsf(a3))) + 0.01f;
        }
        int m = blockIdx.x * PTS + p;
        *(float4*)(out + m * 8 + og) = make_float4(a0, a1, a2, a3);
    }
}

// ---------------- host launch ----------------
extern "C" void kernel_launch(void* const* d_in, const int* in_sizes, int n_in,
                              void* d_out, int out_size) {
    const float* coords   = (const float*)d_in[0];
    const float* z_grid   = (const float*)d_in[1];
    const float* fourierB = (const float*)d_in[2];
    const float* W1   = (const float*)d_in[3];
    const float* b1   = (const float*)d_in[4];
    const float* W2   = (const float*)d_in[5];
    const float* b2   = (const float*)d_in[6];
    const float* W3   = (const float*)d_in[7];
    const float* b3   = (const float*)d_in[8];
    const float* Wvel = (const float*)d_in[9];
    const float* bvel = (const float*)d_in[10];
    const float* Wfh  = (const float*)d_in[11];
    const float* bfh  = (const float*)d_in[12];
    const float* Wph  = (const float*)d_in[13];
    const float* bph  = (const float*)d_in[14];
    const float* Wmu  = (const float*)d_in[15];
    const float* bmu  = (const float*)d_in[16];
    const float* Wstd = (const float*)d_in[17];
    const float* bstd = (const float*)d_in[18];
    float* out = (float*)d_out;

    static bool attr_set = false;
    if (!attr_set) {
        cudaFuncSetAttribute(pinn_main, cudaFuncAttributeMaxDynamicSharedMemorySize, SM_TOTAL);
        attr_set = true;
    }

    transpose_z_kernel<<<(16 * 64 * 64 * 64) / 256, 256>>>(z_grid);
    prep_wfrag_kernel<<<(WF_TOTAL + 255) / 256, 256>>>(W1, b1, W2, W3);
    prep_heads_kernel<<<1, 128>>>(Wvel, bvel, Wfh, bfh, Wph, bph, Wmu, bmu, Wstd, bstd);
    pinn_main<<<NBLK, TPB, SM_TOTAL>>>(coords, fourierB, b2, b3, out);
}

// round 9
// speedup vs baseline: 1.1460x; 1.1460x over previous
#include <cuda_runtime.h>
#include <cuda_fp16.h>
#include <math.h>
#include <stdint.h>

// ---------------- dims ----------------
#define NPTS 131072
#define PTS  64             // points per block
#define TPB  128            // 4 warps, each owns 16 points x full N=128
#define NBLK (NPTS/PTS)     // 2048
#define HID  128
#define L1_KT 13            // K = 208 (194 real + bias row + pad)
#define L23_KT 8            // K = 128

// ---------------- A smem layout (bytes) ----------------
#define SA_STRIDE 432       // feature row stride: 216 fp16 (16B-aligned)
#define SA_HALF   27648     // 64*432, lo buffer offset
#define SM_B2 0             // b2: 128 f32
#define SM_B3 512           // b3: 128 f32
#define SM_A  1024
#define SM_TOTAL (SM_A + 2*SA_HALF)   // 56320

// weight fragment array (uint2 units): [layer][kt][nt 0..15][lane]  (fp16 hi only)
#define WF_L1 0
#define WF_L2 6656          // 13*512
#define WF_L3 10752
#define WF_TOTAL 14848

// ---------------- device scratch ----------------
__device__ float g_zt[16*64*64*64];          // z transposed (B,H,W,C)
__device__ uint2 g_wfrag[WF_TOTAL];          // MMA b-fragments {b0h,b1h} fp16
__device__ float g_wh[HID*8];                // head weights [k][o]
__device__ float g_hb[8];                    // head biases

// ---------------- helpers ----------------
__device__ __forceinline__ uint32_t smem_u32(const void* p) {
    uint32_t a;
    asm("{ .reg .u64 t; cvta.to.shared.u64 t, %1; cvt.u32.u64 %0, t; }" : "=r"(a) : "l"(p));
    return a;
}
__device__ __forceinline__ void ldsm4(uint32_t* r, uint32_t a) {
    asm volatile("ldmatrix.sync.aligned.m8n8.x4.shared.b16 {%0,%1,%2,%3}, [%4];"
                 : "=r"(r[0]), "=r"(r[1]), "=r"(r[2]), "=r"(r[3]) : "r"(a));
}
__device__ __forceinline__ void mma_f16(float* d, const uint32_t* a, uint32_t b0, uint32_t b1) {
    asm volatile("mma.sync.aligned.m16n8k16.row.col.f32.f16.f16.f32 "
                 "{%0,%1,%2,%3}, {%4,%5,%6,%7}, {%8,%9}, {%0,%1,%2,%3};"
                 : "+f"(d[0]), "+f"(d[1]), "+f"(d[2]), "+f"(d[3])
                 : "r"(a[0]), "r"(a[1]), "r"(a[2]), "r"(a[3]), "r"(b0), "r"(b1));
}
// fast tanh: 1 - 2/(exp(2x)+1); ~1e-6 abs err
__device__ __forceinline__ float ftanh(float x) {
    float e = __expf(2.f * x);
    float r;
    asm("rcp.approx.f32 %0, %1;" : "=f"(r) : "f"(e + 1.f));
    return fmaf(-2.f, r, 1.f);
}
// pack (a,b) fp32 pair -> hi fp16x2 word + lo (residual) fp16x2 word; Ah+Al ~exact (22 bits)
__device__ __forceinline__ void split2h(float a, float b, uint32_t& hi, uint32_t& lo) {
    __half ah = __float2half_rn(a), bh = __float2half_rn(b);
    __half al = __float2half_rn(a - __half2float(ah));
    __half bl = __float2half_rn(b - __half2float(bh));
    hi = (uint32_t)__half_as_ushort(ah) | ((uint32_t)__half_as_ushort(bh) << 16);
    lo = (uint32_t)__half_as_ushort(al) | ((uint32_t)__half_as_ushort(bl) << 16);
}
// fast sin/cos with explicit 2-step 2*pi range reduction
__device__ __forceinline__ void fsincos(float x, float& s, float& c) {
    float k = rintf(x * 0.15915494309189535f);
    float r = fmaf(-k, 6.2831855f, x);
    r = fmaf(-k, -1.7484555e-7f, r);
    s = __sinf(r);
    c = __cosf(r);
}

// ---------------- prologue kernels ----------------
__global__ void __launch_bounds__(256) transpose_z_kernel(const float* __restrict__ z) {
    int i = blockIdx.x * 256 + threadIdx.x;
    int x = i & 63, y = (i >> 6) & 63, c = (i >> 12) & 63, b = i >> 18;
    g_zt[(((((b << 6) + y) << 6) + x) << 6) + c] = z[i];
}

// Pre-pack weights into MMA col-major b-fragment layout (fp16 hi only).
// lane l, n-tile nt, k-tile kt:  n = nt*8 + l/4,  k0 = kt*16 + (l%4)*2
__global__ void __launch_bounds__(256) prep_wfrag_kernel(
    const float* __restrict__ W1, const float* __restrict__ b1,
    const float* __restrict__ W2, const float* __restrict__ W3)
{
    int i = blockIdx.x * 256 + threadIdx.x;
    if (i >= WF_TOTAL) return;
    int layer, rem;
    const float* W;
    if (i < WF_L2)      { layer = 1; rem = i;          W = W1; }
    else if (i < WF_L3) { layer = 2; rem = i - WF_L2;  W = W2; }
    else                { layer = 3; rem = i - WF_L3;  W = W3; }
    int lane = rem & 31, nt = (rem >> 5) & 15, kt = rem >> 9;
    int n  = nt * 8 + (lane >> 2);
    int k0 = kt * 16 + (lane & 3) * 2;
    float v[4];
    #pragma unroll
    for (int j = 0; j < 4; j++) {
        int k = k0 + (j >> 1) * 8 + (j & 1);
        float val;
        if (layer == 1) {
            if (k < 194)       val = W[k * HID + n];
            else if (k == 194) val = b1[n];
            else               val = 0.f;
        } else {
            val = W[k * HID + n];
        }
        v[j] = val;
    }
    uint2 o;
    o.x = (uint32_t)__half_as_ushort(__float2half_rn(v[0]))
        | ((uint32_t)__half_as_ushort(__float2half_rn(v[1])) << 16);
    o.y = (uint32_t)__half_as_ushort(__float2half_rn(v[2]))
        | ((uint32_t)__half_as_ushort(__float2half_rn(v[3])) << 16);
    g_wfrag[i] = o;
}

__global__ void __launch_bounds__(128) prep_heads_kernel(
    const float* __restrict__ Wvel, const float* __restrict__ bvel,
    const float* __restrict__ Wfh,  const float* __restrict__ bfh,
    const float* __restrict__ Wph,  const float* __restrict__ bph,
    const float* __restrict__ Wmu,  const float* __restrict__ bmu,
    const float* __restrict__ Wstd, const float* __restrict__ bstd)
{
    int k = threadIdx.x;
    g_wh[k * 8 + 0] = Wvel[k * 2 + 0];
    g_wh[k * 8 + 1] = Wvel[k * 2 + 1];
    g_wh[k * 8 + 2] = Wfh[k * 2 + 0];
    g_wh[k * 8 + 3] = Wfh[k * 2 + 1];
    g_wh[k * 8 + 4] = Wph[k * 2 + 0];
    g_wh[k * 8 + 5] = Wph[k * 2 + 1];
    g_wh[k * 8 + 6] = Wmu[k];
    g_wh[k * 8 + 7] = Wstd[k];
    if (k < 8) {
        float hb;
        if      (k < 2)  hb = bvel[k];
        else if (k < 4)  hb = bfh[k - 2];
        else if (k < 6)  hb = bph[k - 4];
        else if (k == 6) hb = bmu[0];
        else             hb = bstd[0];
        g_hb[k] = hb;
    }
}

// interleaved group of 4 n-tiles: 2 products (AhBh + AlBh), dep distance 4
__device__ __forceinline__ void mma_group4(float (*d)[4], const uint32_t* Ah, const uint32_t* Al,
                                           const uint2* p, int ntBase) {
    uint2 B0 = __ldg(p + (ntBase + 0) * 32);
    uint2 B1 = __ldg(p + (ntBase + 1) * 32);
    uint2 B2 = __ldg(p + (ntBase + 2) * 32);
    uint2 B3 = __ldg(p + (ntBase + 3) * 32);
    float* d0 = d[ntBase + 0];
    float* d1 = d[ntBase + 1];
    float* d2 = d[ntBase + 2];
    float* d3 = d[ntBase + 3];
    mma_f16(d0, Ah, B0.x, B0.y);
    mma_f16(d1, Ah, B1.x, B1.y);
    mma_f16(d2, Ah, B2.x, B2.y);
    mma_f16(d3, Ah, B3.x, B3.y);
    mma_f16(d0, Al, B0.x, B0.y);
    mma_f16(d1, Al, B1.x, B1.y);
    mma_f16(d2, Al, B2.x, B2.y);
    mma_f16(d3, Al, B3.x, B3.y);
}

// ---------------- main kernel ----------------
__global__ void __launch_bounds__(TPB, 3) pinn_main(
    const float* __restrict__ coords, const float* __restrict__ fourierB,
    const float* __restrict__ b2g, const float* __restrict__ b3g,
    float* __restrict__ out)
{
    extern __shared__ __align__(16) unsigned char smem[];
    const uint32_t sb = smem_u32(smem);
    const int tid  = threadIdx.x;
    const int lane = tid & 31;
    const int warp = tid >> 5;        // 0..3, owns rows warp*16..warp*16+15

    float* sb2 = (float*)(smem + SM_B2);
    float* sb3 = (float*)(smem + SM_B3);
    sb2[tid] = b2g[tid];
    sb3[tid] = b3g[tid];

    // ---- feature build: 2 threads per point (64 points) ----
    {
        int p = tid >> 1, role = tid & 1;
        int m = blockIdx.x * PTS + p;
        uint32_t rowOff = SM_A + (uint32_t)p * SA_STRIDE;
        if (role == 0) {
            float cx = coords[m * 3 + 0], cy = coords[m * 3 + 1];
            int b = m >> 13;
            float fx = (cx + 1.f) * 0.5f * 63.f;
            float fy = (cy + 1.f) * 0.5f * 63.f;
            float x0f = floorf(fx), y0f = floorf(fy);
            int x0 = min(max((int)x0f, 0), 63);
            int x1 = max(min((int)x0f + 1, 63), 0);
            int y0 = min(max((int)y0f, 0), 63);
            int y1 = max(min((int)y0f + 1, 63), 0);
            float wa = (x0f + 1.f - fx) * (y0f + 1.f - fy);
            float wb = (x0f + 1.f - fx) * (fy - y0f);
            float wc = (fx - x0f) * (y0f + 1.f - fy);
            float wd = (fx - x0f) * (fy - y0f);
            const float4* p00 = (const float4*)(g_zt + ((((b << 6) + y0) << 6) + x0) * 64);
            const float4* p01 = (const float4*)(g_zt + ((((b << 6) + y1) << 6) + x0) * 64);
            const float4* p10 = (const float4*)(g_zt + ((((b << 6) + y0) << 6) + x1) * 64);
            const float4* p11 = (const float4*)(g_zt + ((((b << 6) + y1) << 6) + x1) * 64);
            #pragma unroll
            for (int g = 0; g < 16; g++) {
                float4 A = p00[g], B = p01[g], C = p10[g], D = p11[g];
                float v0 = wa*A.x + wb*B.x + wc*C.x + wd*D.x;
                float v1 = wa*A.y + wb*B.y + wc*C.y + wd*D.y;
                float v2 = wa*A.z + wb*B.z + wc*C.z + wd*D.z;
                float v3 = wa*A.w + wb*B.w + wc*C.w + wd*D.w;
                uint32_t h0, l0, h1, l1;
                split2h(v0, v1, h0, l0);
                split2h(v2, v3, h1, l1);
                *(uint32_t*)(smem + rowOff + g * 8)               = h0;
                *(uint32_t*)(smem + rowOff + g * 8 + 4)           = h1;
                *(uint32_t*)(smem + rowOff + SA_HALF + g * 8)     = l0;
                *(uint32_t*)(smem + rowOff + SA_HALF + g * 8 + 4) = l1;
            }
            // tail: cols 192..207 -> (cx,cy), (1,0), zeros
            uint32_t h, l;
            split2h(cx, cy, h, l);
            *(uint32_t*)(smem + rowOff + 384)           = h;
            *(uint32_t*)(smem + rowOff + SA_HALF + 384) = l;
            split2h(1.f, 0.f, h, l);
            *(uint32_t*)(smem + rowOff + 388)           = h;
            *(uint32_t*)(smem + rowOff + SA_HALF + 388) = l;
            #pragma unroll
            for (int w = 0; w < 6; w++) {
                *(uint32_t*)(smem + rowOff + 392 + w * 4)           = 0;
                *(uint32_t*)(smem + rowOff + SA_HALF + 392 + w * 4) = 0;
            }
        } else {
            float ct = coords[m * 3 + 2];
            const float tscale = 2.0943951023931953f * ct;  // 2*pi/TEMPORAL_MAX * t
            #pragma unroll 8
            for (int f = 0; f < 32; f++) {
                float s0, c0, s1, c1;
                fsincos(fourierB[2 * f]     * tscale, s0, c0);
                fsincos(fourierB[2 * f + 1] * tscale, s1, c1);
                uint32_t hs, ls, hc, lc;
                split2h(s0, s1, hs, ls);
                split2h(c0, c1, hc, lc);
                *(uint32_t*)(smem + rowOff + 128 + f * 4)           = hs;  // cols 64..127
                *(uint32_t*)(smem + rowOff + SA_HALF + 128 + f * 4) = ls;
                *(uint32_t*)(smem + rowOff + 256 + f * 4)           = hc;  // cols 128..191
                *(uint32_t*)(smem + rowOff + SA_HALF + 256 + f * 4) = lc;
            }
        }
    }
    __syncthreads();   // features + biases ready; after this, warps are independent

    // ldmatrix A address for this warp's 16 rows
    const uint32_t aAddr = sb + SM_A + (uint32_t)(warp * 16 + (lane & 15)) * SA_STRIDE + (lane >> 4) * 16;

    float d[16][4];

    // ================= layer 1 (A from smem) =================
    #pragma unroll
    for (int nt = 0; nt < 16; nt++)
        #pragma unroll
        for (int i = 0; i < 4; i++) d[nt][i] = 0.f;
    {
        const uint2* wf = g_wfrag + WF_L1 + lane;
        #pragma unroll 1
        for (int kt = 0; kt < L1_KT; kt++) {
            uint32_t Ah[4], Al[4];
            ldsm4(Ah, aAddr + kt * 32);
            ldsm4(Al, aAddr + kt * 32 + SA_HALF);
            const uint2* p = wf + kt * 512;
            #pragma unroll
            for (int ng = 0; ng < 4; ng++)
                mma_group4(d, Ah, Al, p, 4 * ng);
        }
    }

    // epilogue 1 -> A2 in registers (bias folded into W1); D-frag == A-frag layout
    uint32_t A2h[8][4], A2l[8][4];
    #pragma unroll
    for (int kt = 0; kt < 8; kt++)
        #pragma unroll
        for (int j = 0; j < 4; j++) {
            int srcnt = 2 * kt + (j >> 1);
            int c = (j & 1) * 2;
            split2h(ftanh(d[srcnt][c]), ftanh(d[srcnt][c + 1]), A2h[kt][j], A2l[kt][j]);
        }

    // ================= layer 2 (A in registers) =================
    #pragma unroll
    for (int nt = 0; nt < 16; nt++)
        #pragma unroll
        for (int i = 0; i < 4; i++) d[nt][i] = 0.f;
    {
        const uint2* wf = g_wfrag + WF_L2 + lane;
        #pragma unroll 1
        for (int kt = 0; kt < L23_KT; kt++) {
            const uint2* p = wf + kt * 512;
            #pragma unroll
            for (int ng = 0; ng < 4; ng++)
                mma_group4(d, A2h[kt], A2l[kt], p, 4 * ng);
        }
    }

    // epilogue 2: +b2, tanh -> A3 (reuse A2 arrays)
    #pragma unroll
    for (int kt = 0; kt < 8; kt++)
        #pragma unroll
        for (int j = 0; j < 4; j++) {
            int srcnt = 2 * kt + (j >> 1);
            int c = (j & 1) * 2;
            int col = 8 * srcnt + (lane & 3) * 2;
            float2 bb = *(float2*)(sb2 + col);
            split2h(ftanh(d[srcnt][c] + bb.x), ftanh(d[srcnt][c + 1] + bb.y),
                    A2h[kt][j], A2l[kt][j]);
        }

    // ================= layer 3 (A in registers) =================
    #pragma unroll
    for (int nt = 0; nt < 16; nt++)
        #pragma unroll
        for (int i = 0; i < 4; i++) d[nt][i] = 0.f;
    {
        const uint2* wf = g_wfrag + WF_L3 + lane;
        #pragma unroll 1
        for (int kt = 0; kt < L23_KT; kt++) {
            const uint2* p = wf + kt * 512;
            #pragma unroll
            for (int ng = 0; ng < 4; ng++)
                mma_group4(d, A2h[kt], A2l[kt], p, 4 * ng);
        }
    }

    // epilogue 3: +b3, tanh -> fp32 feat in smem (stride 132 floats)
    {
        float* featF = (float*)(smem + SM_A);
        int row0 = warp * 16 + (lane >> 2);
        #pragma unroll
        for (int nt = 0; nt < 16; nt++) {
            int col = 8 * nt + (lane & 3) * 2;
            float2 bb = *(float2*)(sb3 + col);
            *(float2*)(featF + row0 * 132 + col) =
                make_float2(ftanh(d[nt][0] + bb.x), ftanh(d[nt][1] + bb.y));
            *(float2*)(featF + (row0 + 8) * 132 + col) =
                make_float2(ftanh(d[nt][2] + bb.x), ftanh(d[nt][3] + bb.y));
        }
    }
    __syncthreads();

    // ================= heads =================
    {
        const float* featF = (const float*)(smem + SM_A);
        int p = tid >> 1;
        int og = (tid & 1) * 4;
        const float4* wh4 = (const float4*)g_wh;
        float a0 = 0.f, a1 = 0.f, a2 = 0.f, a3 = 0.f;
        #pragma unroll 4
        for (int k = 0; k < HID; k++) {
            float f = featF[p * 132 + k];
            float4 w = __ldg(wh4 + k * 2 + (tid & 1));
            a0 += f * w.x; a1 += f * w.y; a2 += f * w.z; a3 += f * w.w;
        }
        a0 += g_hb[og]; a1 += g_hb[og + 1]; a2 += g_hb[og + 2]; a3 += g_hb[og + 3];
        if (og == 4) {  // output 7 = softplus(.) + MIN_STD
            a3 = fmaxf(a3, 0.f) + log1pf(expf(-fabsf(a3))) + 0.01f;
        }
        int m = blockIdx.x * PTS + p;
        *(float4*)(out + m * 8 + og) = make_float4(a0, a1, a2, a3);
    }
}

// ---------------- host launch ----------------
extern "C" void kernel_launch(void* const* d_in, const int* in_sizes, int n_in,
                              void* d_out, int out_size) {
    const float* coords   = (const float*)d_in[0];
    const float* z_grid   = (const float*)d_in[1];
    const float* fourierB = (const float*)d_in[2];
    const float* W1   = (const float*)d_in[3];
    const float* b1   = (const float*)d_in[4];
    const float* W2   = (const float*)d_in[5];
    const float* b2   = (const float*)d_in[6];
    const float* W3   = (const float*)d_in[7];
    const float* b3   = (const float*)d_in[8];
    const float* Wvel = (const float*)d_in[9];
    const float* bvel = (const float*)d_in[10];
    const float* Wfh  = (const float*)d_in[11];
    const float* bfh  = (const float*)d_in[12];
    const float* Wph  = (const float*)d_in[13];
    const float* bph  = (const float*)d_in[14];
    const float* Wmu  = (const float*)d_in[15];
    const float* bmu  = (const float*)d_in[16];
    const float* Wstd = (const float*)d_in[17];
    const float* bstd = (const float*)d_in[18];
    float* out = (float*)d_out;

    static bool attr_set = false;
    if (!attr_set) {
        cudaFuncSetAttribute(pinn_main, cudaFuncAttributeMaxDynamicSharedMemorySize, SM_TOTAL);
        attr_set = true;
    }

    transpose_z_kernel<<<(16 * 64 * 64 * 64) / 256, 256>>>(z_grid);
    prep_wfrag_kernel<<<(WF_TOTAL + 255) / 256, 256>>>(W1, b1, W2, W3);
    prep_heads_kernel<<<1, 128>>>(Wvel, bvel, Wfh, bfh, Wph, bph, Wmu, bmu, Wstd, bstd);
    pinn_main<<<NBLK, TPB, SM_TOTAL>>>(coords, fourierB, b2, b3, out);
}

// round 10
// speedup vs baseline: 1.3358x; 1.1656x over previous
#include <cuda_runtime.h>
#include <cuda_fp16.h>
#include <math.h>
#include <stdint.h>

// ---------------- dims ----------------
#define NPTS 131072
#define PTS  64             // points per block
#define TPB  128            // 4 warps, each owns 16 points x full N=128
#define NBLK (NPTS/PTS)     // 2048
#define HID  128
#define L1_KT 13            // K = 208 (194 real + bias row + pad)
#define L23_KT 8            // K = 128

// ---------------- A smem layout (bytes) ----------------
#define SA_STRIDE 432       // feature row stride: 216 fp16 (16B-aligned)
#define SA_HALF   27648     // 64*432, lo buffer offset
#define SM_B2 0             // b2: 128 f32
#define SM_B3 512           // b3: 128 f32
#define SM_A  1024
#define SM_TOTAL (SM_A + 2*SA_HALF)   // 56320

// weight fragment array (uint2 units): [layer][kt][nt 0..15][lane]  (fp16 hi only)
#define WF_L1 0
#define WF_L2 6656          // 13*512
#define WF_L3 10752
#define WF_TOTAL 14848

// ---------------- device scratch ----------------
__device__ float g_zt[16*64*64*64];          // z transposed (B,H,W,C)
__device__ uint2 g_wfrag[WF_TOTAL];          // MMA b-fragments {b0h,b1h} fp16
__device__ uint4 g_hfrag[8*32];              // head b-fragments {b0h,b1h,b0l,b1l}
__device__ float g_hb[8];                    // head biases

// ---------------- helpers ----------------
__device__ __forceinline__ uint32_t smem_u32(const void* p) {
    uint32_t a;
    asm("{ .reg .u64 t; cvta.to.shared.u64 t, %1; cvt.u32.u64 %0, t; }" : "=r"(a) : "l"(p));
    return a;
}
__device__ __forceinline__ void ldsm4(uint32_t* r, uint32_t a) {
    asm volatile("ldmatrix.sync.aligned.m8n8.x4.shared.b16 {%0,%1,%2,%3}, [%4];"
                 : "=r"(r[0]), "=r"(r[1]), "=r"(r[2]), "=r"(r[3]) : "r"(a));
}
__device__ __forceinline__ void mma_f16(float* d, const uint32_t* a, uint32_t b0, uint32_t b1) {
    asm volatile("mma.sync.aligned.m16n8k16.row.col.f32.f16.f16.f32 "
                 "{%0,%1,%2,%3}, {%4,%5,%6,%7}, {%8,%9}, {%0,%1,%2,%3};"
                 : "+f"(d[0]), "+f"(d[1]), "+f"(d[2]), "+f"(d[3])
                 : "r"(a[0]), "r"(a[1]), "r"(a[2]), "r"(a[3]), "r"(b0), "r"(b1));
}
// fast tanh: 1 - 2/(exp(2x)+1); ~1e-6 abs err
__device__ __forceinline__ float ftanh(float x) {
    float e = __expf(2.f * x);
    float r;
    asm("rcp.approx.f32 %0, %1;" : "=f"(r) : "f"(e + 1.f));
    return fmaf(-2.f, r, 1.f);
}
// pack (a,b) fp32 pair -> hi fp16x2 word + lo (residual) fp16x2 word
__device__ __forceinline__ void split2h(float a, float b, uint32_t& hi, uint32_t& lo) {
    __half ah = __float2half_rn(a), bh = __float2half_rn(b);
    __half al = __float2half_rn(a - __half2float(ah));
    __half bl = __float2half_rn(b - __half2float(bh));
    hi = (uint32_t)__half_as_ushort(ah) | ((uint32_t)__half_as_ushort(bh) << 16);
    lo = (uint32_t)__half_as_ushort(al) | ((uint32_t)__half_as_ushort(bl) << 16);
}
// fast sin/cos with explicit 2-step 2*pi range reduction
__device__ __forceinline__ void fsincos(float x, float& s, float& c) {
    float k = rintf(x * 0.15915494309189535f);
    float r = fmaf(-k, 6.2831855f, x);
    r = fmaf(-k, -1.7484555e-7f, r);
    s = __sinf(r);
    c = __cosf(r);
}

// ---------------- prologue kernels ----------------
__global__ void __launch_bounds__(256) transpose_z_kernel(const float* __restrict__ z) {
    int i = blockIdx.x * 256 + threadIdx.x;
    int x = i & 63, y = (i >> 6) & 63, c = (i >> 12) & 63, b = i >> 18;
    g_zt[(((((b << 6) + y) << 6) + x) << 6) + c] = z[i];
}

// Pre-pack trunk weights into MMA col-major b-fragment layout (fp16 hi only).
__global__ void __launch_bounds__(256) prep_wfrag_kernel(
    const float* __restrict__ W1, const float* __restrict__ b1,
    const float* __restrict__ W2, const float* __restrict__ W3)
{
    int i = blockIdx.x * 256 + threadIdx.x;
    if (i >= WF_TOTAL) return;
    int layer, rem;
    const float* W;
    if (i < WF_L2)      { layer = 1; rem = i;          W = W1; }
    else if (i < WF_L3) { layer = 2; rem = i - WF_L2;  W = W2; }
    else                { layer = 3; rem = i - WF_L3;  W = W3; }
    int lane = rem & 31, nt = (rem >> 5) & 15, kt = rem >> 9;
    int n  = nt * 8 + (lane >> 2);
    int k0 = kt * 16 + (lane & 3) * 2;
    float v[4];
    #pragma unroll
    for (int j = 0; j < 4; j++) {
        int k = k0 + (j >> 1) * 8 + (j & 1);
        float val;
        if (layer == 1) {
            if (k < 194)       val = W[k * HID + n];
            else if (k == 194) val = b1[n];
            else               val = 0.f;
        } else {
            val = W[k * HID + n];
        }
        v[j] = val;
    }
    uint2 o;
    o.x = (uint32_t)__half_as_ushort(__float2half_rn(v[0]))
        | ((uint32_t)__half_as_ushort(__float2half_rn(v[1])) << 16);
    o.y = (uint32_t)__half_as_ushort(__float2half_rn(v[2]))
        | ((uint32_t)__half_as_ushort(__float2half_rn(v[3])) << 16);
    g_wfrag[i] = o;
}

// head weight for output col n, input k
__device__ __forceinline__ float head_w(int k, int n,
    const float* Wvel, const float* Wfh, const float* Wph,
    const float* Wmu, const float* Wstd)
{
    if (n < 2) return Wvel[k * 2 + n];
    if (n < 4) return Wfh[k * 2 + n - 2];
    if (n < 6) return Wph[k * 2 + n - 4];
    if (n == 6) return Wmu[k];
    return Wstd[k];
}

// head fragments: 8 kt x 32 lanes, nt=0 (cols 0..7), hi+lo split
__global__ void __launch_bounds__(256) prep_heads_kernel(
    const float* __restrict__ Wvel, const float* __restrict__ bvel,
    const float* __restrict__ Wfh,  const float* __restrict__ bfh,
    const float* __restrict__ Wph,  const float* __restrict__ bph,
    const float* __restrict__ Wmu,  const float* __restrict__ bmu,
    const float* __restrict__ Wstd, const float* __restrict__ bstd)
{
    int i = threadIdx.x;               // 0..255 = kt*32 + lane
    int lane = i & 31, kt = i >> 5;
    int n  = lane >> 2;
    int k0 = kt * 16 + (lane & 3) * 2;
    float v[4];
    #pragma unroll
    for (int j = 0; j < 4; j++) {
        int k = k0 + (j >> 1) * 8 + (j & 1);
        v[j] = head_w(k, n, Wvel, Wfh, Wph, Wmu, Wstd);
    }
    uint4 o;
    split2h(v[0], v[1], o.x, o.z);
    split2h(v[2], v[3], o.y, o.w);
    g_hfrag[i] = o;
    if (i < 8) {
        float hb;
        if      (i < 2)  hb = bvel[i];
        else if (i < 4)  hb = bfh[i - 2];
        else if (i < 6)  hb = bph[i - 4];
        else if (i == 6) hb = bmu[0];
        else             hb = bstd[0];
        g_hb[i] = hb;
    }
}

// interleaved group of 4 n-tiles: 2 products (AhBh + AlBh), dep distance 4
__device__ __forceinline__ void mma_group4(float (*d)[4], const uint32_t* Ah, const uint32_t* Al,
                                           const uint2* p, int ntBase) {
    uint2 B0 = __ldg(p + (ntBase + 0) * 32);
    uint2 B1 = __ldg(p + (ntBase + 1) * 32);
    uint2 B2 = __ldg(p + (ntBase + 2) * 32);
    uint2 B3 = __ldg(p + (ntBase + 3) * 32);
    float* d0 = d[ntBase + 0];
    float* d1 = d[ntBase + 1];
    float* d2 = d[ntBase + 2];
    float* d3 = d[ntBase + 3];
    mma_f16(d0, Ah, B0.x, B0.y);
    mma_f16(d1, Ah, B1.x, B1.y);
    mma_f16(d2, Ah, B2.x, B2.y);
    mma_f16(d3, Ah, B3.x, B3.y);
    mma_f16(d0, Al, B0.x, B0.y);
    mma_f16(d1, Al, B1.x, B1.y);
    mma_f16(d2, Al, B2.x, B2.y);
    mma_f16(d3, Al, B3.x, B3.y);
}

// ---------------- main kernel ----------------
__global__ void __launch_bounds__(TPB, 3) pinn_main(
    const float* __restrict__ coords, const float* __restrict__ fourierB,
    const float* __restrict__ b2g, const float* __restrict__ b3g,
    float* __restrict__ out)
{
    extern __shared__ __align__(16) unsigned char smem[];
    const uint32_t sb = smem_u32(smem);
    const int tid  = threadIdx.x;
    const int lane = tid & 31;
    const int warp = tid >> 5;        // 0..3, owns rows warp*16..warp*16+15

    float* sb2 = (float*)(smem + SM_B2);
    float* sb3 = (float*)(smem + SM_B3);
    sb2[tid] = b2g[tid];
    sb3[tid] = b3g[tid];

    // ---- feature build: 2 threads per point (64 points) ----
    {
        int p = tid >> 1, role = tid & 1;
        int m = blockIdx.x * PTS + p;
        uint32_t rowOff = SM_A + (uint32_t)p * SA_STRIDE;
        if (role == 0) {
            float cx = coords[m * 3 + 0], cy = coords[m * 3 + 1];
            int b = m >> 13;
            float fx = (cx + 1.f) * 0.5f * 63.f;
            float fy = (cy + 1.f) * 0.5f * 63.f;
            float x0f = floorf(fx), y0f = floorf(fy);
            int x0 = min(max((int)x0f, 0), 63);
            int x1 = max(min((int)x0f + 1, 63), 0);
            int y0 = min(max((int)y0f, 0), 63);
            int y1 = max(min((int)y0f + 1, 63), 0);
            float wa = (x0f + 1.f - fx) * (y0f + 1.f - fy);
            float wb = (x0f + 1.f - fx) * (fy - y0f);
            float wc = (fx - x0f) * (y0f + 1.f - fy);
            float wd = (fx - x0f) * (fy - y0f);
            const float4* p00 = (const float4*)(g_zt + ((((b << 6) + y0) << 6) + x0) * 64);
            const float4* p01 = (const float4*)(g_zt + ((((b << 6) + y1) << 6) + x0) * 64);
            const float4* p10 = (const float4*)(g_zt + ((((b << 6) + y0) << 6) + x1) * 64);
            const float4* p11 = (const float4*)(g_zt + ((((b << 6) + y1) << 6) + x1) * 64);
            #pragma unroll
            for (int g = 0; g < 16; g++) {
                float4 A = p00[g], B = p01[g], C = p10[g], D = p11[g];
                float v0 = wa*A.x + wb*B.x + wc*C.x + wd*D.x;
                float v1 = wa*A.y + wb*B.y + wc*C.y + wd*D.y;
                float v2 = wa*A.z + wb*B.z + wc*C.z + wd*D.z;
                float v3 = wa*A.w + wb*B.w + wc*C.w + wd*D.w;
                uint32_t h0, l0, h1, l1;
                split2h(v0, v1, h0, l0);
                split2h(v2, v3, h1, l1);
                *(uint32_t*)(smem + rowOff + g * 8)               = h0;
                *(uint32_t*)(smem + rowOff + g * 8 + 4)           = h1;
                *(uint32_t*)(smem + rowOff + SA_HALF + g * 8)     = l0;
                *(uint32_t*)(smem + rowOff + SA_HALF + g * 8 + 4) = l1;
            }
            // tail: cols 192..207 -> (cx,cy), (1,0), zeros
            uint32_t h, l;
            split2h(cx, cy, h, l);
            *(uint32_t*)(smem + rowOff + 384)           = h;
            *(uint32_t*)(smem + rowOff + SA_HALF + 384) = l;
            split2h(1.f, 0.f, h, l);
            *(uint32_t*)(smem + rowOff + 388)           = h;
            *(uint32_t*)(smem + rowOff + SA_HALF + 388) = l;
            #pragma unroll
            for (int w = 0; w < 6; w++) {
                *(uint32_t*)(smem + rowOff + 392 + w * 4)           = 0;
                *(uint32_t*)(smem + rowOff + SA_HALF + 392 + w * 4) = 0;
            }
        } else {
            float ct = coords[m * 3 + 2];
            const float tscale = 2.0943951023931953f * ct;  // 2*pi/TEMPORAL_MAX * t
            #pragma unroll 8
            for (int f = 0; f < 32; f++) {
                float s0, c0, s1, c1;
                fsincos(fourierB[2 * f]     * tscale, s0, c0);
                fsincos(fourierB[2 * f + 1] * tscale, s1, c1);
                uint32_t hs, ls, hc, lc;
                split2h(s0, s1, hs, ls);
                split2h(c0, c1, hc, lc);
                *(uint32_t*)(smem + rowOff + 128 + f * 4)           = hs;  // cols 64..127
                *(uint32_t*)(smem + rowOff + SA_HALF + 128 + f * 4) = ls;
                *(uint32_t*)(smem + rowOff + 256 + f * 4)           = hc;  // cols 128..191
                *(uint32_t*)(smem + rowOff + SA_HALF + 256 + f * 4) = lc;
            }
        }
    }
    __syncthreads();   // features + biases ready; after this, warps are independent

    // ldmatrix A address for this warp's 16 rows
    const uint32_t aAddr = sb + SM_A + (uint32_t)(warp * 16 + (lane & 15)) * SA_STRIDE + (lane >> 4) * 16;

    float d[16][4];

    // ================= layer 1 (A from smem) =================
    #pragma unroll
    for (int nt = 0; nt < 16; nt++)
        #pragma unroll
        for (int i = 0; i < 4; i++) d[nt][i] = 0.f;
    {
        const uint2* wf = g_wfrag + WF_L1 + lane;
        #pragma unroll 1
        for (int kt = 0; kt < L1_KT; kt++) {
            uint32_t Ah[4], Al[4];
            ldsm4(Ah, aAddr + kt * 32);
            ldsm4(Al, aAddr + kt * 32 + SA_HALF);
            const uint2* p = wf + kt * 512;
            #pragma unroll
            for (int ng = 0; ng < 4; ng++)
                mma_group4(d, Ah, Al, p, 4 * ng);
        }
    }

    // epilogue 1 -> A2 in registers (bias folded into W1); D-frag == A-frag layout
    uint32_t A2h[8][4], A2l[8][4];
    #pragma unroll
    for (int kt = 0; kt < 8; kt++)
        #pragma unroll
        for (int j = 0; j < 4; j++) {
            int srcnt = 2 * kt + (j >> 1);
            int c = (j & 1) * 2;
            split2h(ftanh(d[srcnt][c]), ftanh(d[srcnt][c + 1]), A2h[kt][j], A2l[kt][j]);
        }

    // ================= layer 2 (A in registers) =================
    #pragma unroll
    for (int nt = 0; nt < 16; nt++)
        #pragma unroll
        for (int i = 0; i < 4; i++) d[nt][i] = 0.f;
    {
        const uint2* wf = g_wfrag + WF_L2 + lane;
        #pragma unroll 1
        for (int kt = 0; kt < L23_KT; kt++) {
            const uint2* p = wf + kt * 512;
            #pragma unroll
            for (int ng = 0; ng < 4; ng++)
                mma_group4(d, A2h[kt], A2l[kt], p, 4 * ng);
        }
    }

    // epilogue 2: +b2, tanh -> A3 (reuse A2 arrays)
    #pragma unroll
    for (int kt = 0; kt < 8; kt++)
        #pragma unroll
        for (int j = 0; j < 4; j++) {
            int srcnt = 2 * kt + (j >> 1);
            int c = (j & 1) * 2;
            int col = 8 * srcnt + (lane & 3) * 2;
            float2 bb = *(float2*)(sb2 + col);
            split2h(ftanh(d[srcnt][c] + bb.x), ftanh(d[srcnt][c + 1] + bb.y),
                    A2h[kt][j], A2l[kt][j]);
        }

    // ================= layer 3 (A in registers) =================
    #pragma unroll
    for (int nt = 0; nt < 16; nt++)
        #pragma unroll
        for (int i = 0; i < 4; i++) d[nt][i] = 0.f;
    {
        const uint2* wf = g_wfrag + WF_L3 + lane;
        #pragma unroll 1
        for (int kt = 0; kt < L23_KT; kt++) {
            const uint2* p = wf + kt * 512;
            #pragma unroll
            for (int ng = 0; ng < 4; ng++)
                mma_group4(d, A2h[kt], A2l[kt], p, 4 * ng);
        }
    }

    // epilogue 3: +b3, tanh -> A4 in registers (reuse A2 arrays)
    #pragma unroll
    for (int kt = 0; kt < 8; kt++)
        #pragma unroll
        for (int j = 0; j < 4; j++) {
            int srcnt = 2 * kt + (j >> 1);
            int c = (j & 1) * 2;
            int col = 8 * srcnt + (lane & 3) * 2;
            float2 bb = *(float2*)(sb3 + col);
            split2h(ftanh(d[srcnt][c] + bb.x), ftanh(d[srcnt][c + 1] + bb.y),
                    A2h[kt][j], A2l[kt][j]);
        }

    // ================= heads as MMA (N=8, 3 products for accuracy) =================
    {
        float dh[4] = {0.f, 0.f, 0.f, 0.f};
        const uint4* hf = g_hfrag + lane;
        #pragma unroll
        for (int kt = 0; kt < 8; kt++) {
            uint4 HW = __ldg(hf + kt * 32);
            mma_f16(dh, A2h[kt], HW.x, HW.y);   // AhWh
            mma_f16(dh, A2l[kt], HW.x, HW.y);   // AlWh
            mma_f16(dh, A2h[kt], HW.z, HW.w);   // AhWl
        }
        int c0 = (lane & 3) * 2;
        int r0 = blockIdx.x * PTS + warp * 16 + (lane >> 2);
        float hb0 = g_hb[c0], hb1 = g_hb[c0 + 1];
        float a0 = dh[0] + hb0, a1 = dh[1] + hb1;
        float a2 = dh[2] + hb0, a3 = dh[3] + hb1;
        if (c0 == 6) {   // col 7 = softplus(.) + MIN_STD
            a1 = fmaxf(a1, 0.f) + log1pf(expf(-fabsf(a1))) + 0.01f;
            a3 = fmaxf(a3, 0.f) + log1pf(expf(-fabsf(a3))) + 0.01f;
        }
        *(float2*)(out + r0 * 8 + c0)       = make_float2(a0, a1);
        *(float2*)(out + (r0 + 8) * 8 + c0) = make_float2(a2, a3);
    }
}

// ---------------- host launch ----------------
extern "C" void kernel_launch(void* const* d_in, const int* in_sizes, int n_in,
                              void* d_out, int out_size) {
    const float* coords   = (const float*)d_in[0];
    const float* z_grid   = (const float*)d_in[1];
    const float* fourierB = (const float*)d_in[2];
    const float* W1   = (const float*)d_in[3];
    const float* b1   = (const float*)d_in[4];
    const float* W2   = (const float*)d_in[5];
    const float* b2   = (const float*)d_in[6];
    const float* W3   = (const float*)d_in[7];
    const float* b3   = (const float*)d_in[8];
    const float* Wvel = (const float*)d_in[9];
    const float* bvel = (const float*)d_in[10];
    const float* Wfh  = (const float*)d_in[11];
    const float* bfh  = (const float*)d_in[12];
    const float* Wph  = (const float*)d_in[13];
    const float* bph  = (const float*)d_in[14];
    const float* Wmu  = (const float*)d_in[15];
    const float* bmu  = (const float*)d_in[16];
    const float* Wstd = (const float*)d_in[17];
    const float* bstd = (const float*)d_in[18];
    float* out = (float*)d_out;

    static bool attr_set = false;
    if (!attr_set) {
        cudaFuncSetAttribute(pinn_main, cudaFuncAttributeMaxDynamicSharedMemorySize, SM_TOTAL);
        attr_set = true;
    }

    transpose_z_kernel<<<(16 * 64 * 64 * 64) / 256, 256>>>(z_grid);
    prep_wfrag_kernel<<<(WF_TOTAL + 255) / 256, 256>>>(W1, b1, W2, W3);
    prep_heads_kernel<<<1, 256>>>(Wvel, bvel, Wfh, bfh, Wph, bph, Wmu, bmu, Wstd, bstd);
    pinn_main<<<NBLK, TPB, SM_TOTAL>>>(coords, fourierB, b2, b3, out);
}

// round 11
// speedup vs baseline: 1.5912x; 1.1912x over previous
#include <cuda_runtime.h>
#include <cuda_fp16.h>
#include <math.h>
#include <stdint.h>

// ---------------- dims ----------------
#define NPTS 131072
#define PTS  64             // points per block
#define TPB  128            // 4 warps, each owns 16 points x full N=128
#define NBLK (NPTS/PTS)     // 2048
#define HID  128
#define L1_KT 13            // K = 208 (194 real + bias row + pad)
#define L23_KT 8            // K = 128

// ---------------- A smem layout (bytes) ----------------
#define SA_STRIDE 432       // feature row stride: 216 fp16 (16B-aligned)
#define SM_B2 0             // b2: 128 f32
#define SM_B3 512           // b3: 128 f32
#define SM_A  1024
#define SM_TOTAL (SM_A + 64*SA_STRIDE)   // 28672 -> smem-light; regs cap 3 blocks/SM

// weight fragment array (uint2 units): [layer][kt][nt 0..15][lane]  (fp16 hi only)
#define WF_L1 0
#define WF_L2 6656          // 13*512
#define WF_L3 10752
#define WF_TOTAL 14848

// ---------------- device scratch ----------------
__device__ float g_zt[16*64*64*64];          // z transposed (B,H,W,C)
__device__ uint2 g_wfrag[WF_TOTAL];          // MMA b-fragments {b0h,b1h} fp16
__device__ uint4 g_hfrag[8*32];              // head b-fragments {b0h,b1h,b0l,b1l}
__device__ float g_hb[8];                    // head biases

// ---------------- helpers ----------------
__device__ __forceinline__ uint32_t smem_u32(const void* p) {
    uint32_t a;
    asm("{ .reg .u64 t; cvta.to.shared.u64 t, %1; cvt.u32.u64 %0, t; }" : "=r"(a) : "l"(p));
    return a;
}
__device__ __forceinline__ void ldsm4(uint32_t* r, uint32_t a) {
    asm volatile("ldmatrix.sync.aligned.m8n8.x4.shared.b16 {%0,%1,%2,%3}, [%4];"
                 : "=r"(r[0]), "=r"(r[1]), "=r"(r[2]), "=r"(r[3]) : "r"(a));
}
__device__ __forceinline__ void mma_f16(float* d, const uint32_t* a, uint32_t b0, uint32_t b1) {
    asm volatile("mma.sync.aligned.m16n8k16.row.col.f32.f16.f16.f32 "
                 "{%0,%1,%2,%3}, {%4,%5,%6,%7}, {%8,%9}, {%0,%1,%2,%3};"
                 : "+f"(d[0]), "+f"(d[1]), "+f"(d[2]), "+f"(d[3])
                 : "r"(a[0]), "r"(a[1]), "r"(a[2]), "r"(a[3]), "r"(b0), "r"(b1));
}
// fast tanh: 1 - 2/(exp(2x)+1); ~1e-6 abs err
__device__ __forceinline__ float ftanh(float x) {
    float e = __expf(2.f * x);
    float r;
    asm("rcp.approx.f32 %0, %1;" : "=f"(r) : "f"(e + 1.f));
    return fmaf(-2.f, r, 1.f);
}
// pack (a,b) -> fp16x2 word, low half = a
__device__ __forceinline__ uint32_t packh2(float a, float b) {
    __half2 h = __floats2half2_rn(a, b);
    return *reinterpret_cast<uint32_t*>(&h);
}
// pack (a,b) fp32 pair -> hi fp16x2 word + lo (residual) fp16x2 word
__device__ __forceinline__ void split2h(float a, float b, uint32_t& hi, uint32_t& lo) {
    __half ah = __float2half_rn(a), bh = __float2half_rn(b);
    __half al = __float2half_rn(a - __half2float(ah));
    __half bl = __float2half_rn(b - __half2float(bh));
    hi = (uint32_t)__half_as_ushort(ah) | ((uint32_t)__half_as_ushort(bh) << 16);
    lo = (uint32_t)__half_as_ushort(al) | ((uint32_t)__half_as_ushort(bl) << 16);
}
// fast sin/cos with explicit 2-step 2*pi range reduction
__device__ __forceinline__ void fsincos(float x, float& s, float& c) {
    float k = rintf(x * 0.15915494309189535f);
    float r = fmaf(-k, 6.2831855f, x);
    r = fmaf(-k, -1.7484555e-7f, r);
    s = __sinf(r);
    c = __cosf(r);
}

// ---------------- prologue kernels ----------------
__global__ void __launch_bounds__(256) transpose_z_kernel(const float* __restrict__ z) {
    int i = blockIdx.x * 256 + threadIdx.x;
    int x = i & 63, y = (i >> 6) & 63, c = (i >> 12) & 63, b = i >> 18;
    g_zt[(((((b << 6) + y) << 6) + x) << 6) + c] = z[i];
}

// Pre-pack trunk weights into MMA col-major b-fragment layout (fp16 hi only).
__global__ void __launch_bounds__(256) prep_wfrag_kernel(
    const float* __restrict__ W1, const float* __restrict__ b1,
    const float* __restrict__ W2, const float* __restrict__ W3)
{
    int i = blockIdx.x * 256 + threadIdx.x;
    if (i >= WF_TOTAL) return;
    int layer, rem;
    const float* W;
    if (i < WF_L2)      { layer = 1; rem = i;          W = W1; }
    else if (i < WF_L3) { layer = 2; rem = i - WF_L2;  W = W2; }
    else                { layer = 3; rem = i - WF_L3;  W = W3; }
    int lane = rem & 31, nt = (rem >> 5) & 15, kt = rem >> 9;
    int n  = nt * 8 + (lane >> 2);
    int k0 = kt * 16 + (lane & 3) * 2;
    float v[4];
    #pragma unroll
    for (int j = 0; j < 4; j++) {
        int k = k0 + (j >> 1) * 8 + (j & 1);
        float val;
        if (layer == 1) {
            if (k < 194)       val = W[k * HID + n];
            else if (k == 194) val = b1[n];
            else               val = 0.f;
        } else {
            val = W[k * HID + n];
        }
        v[j] = val;
    }
    uint2 o;
    o.x = packh2(v[0], v[1]);
    o.y = packh2(v[2], v[3]);
    g_wfrag[i] = o;
}

// head weight for output col n, input k
__device__ __forceinline__ float head_w(int k, int n,
    const float* Wvel, const float* Wfh, const float* Wph,
    const float* Wmu, const float* Wstd)
{
    if (n < 2) return Wvel[k * 2 + n];
    if (n < 4) return Wfh[k * 2 + n - 2];
    if (n < 6) return Wph[k * 2 + n - 4];
    if (n == 6) return Wmu[k];
    return Wstd[k];
}

// head fragments: 8 kt x 32 lanes, nt=0 (cols 0..7), hi+lo split
__global__ void __launch_bounds__(256) prep_heads_kernel(
    const float* __restrict__ Wvel, const float* __restrict__ bvel,
    const float* __restrict__ Wfh,  const float* __restrict__ bfh,
    const float* __restrict__ Wph,  const float* __restrict__ bph,
    const float* __restrict__ Wmu,  const float* __restrict__ bmu,
    const float* __restrict__ Wstd, const float* __restrict__ bstd)
{
    int i = threadIdx.x;               // 0..255 = kt*32 + lane
    int lane = i & 31, kt = i >> 5;
    int n  = lane >> 2;
    int k0 = kt * 16 + (lane & 3) * 2;
    float v[4];
    #pragma unroll
    for (int j = 0; j < 4; j++) {
        int k = k0 + (j >> 1) * 8 + (j & 1);
        v[j] = head_w(k, n, Wvel, Wfh, Wph, Wmu, Wstd);
    }
    uint4 o;
    split2h(v[0], v[1], o.x, o.z);
    split2h(v[2], v[3], o.y, o.w);
    g_hfrag[i] = o;
    if (i < 8) {
        float hb;
        if      (i < 2)  hb = bvel[i];
        else if (i < 4)  hb = bfh[i - 2];
        else if (i < 6)  hb = bph[i - 4];
        else if (i == 6) hb = bmu[0];
        else             hb = bstd[0];
        g_hb[i] = hb;
    }
}

// interleaved group of 4 n-tiles: 2 products (AhBh + AlBh)
__device__ __forceinline__ void mma_group4(float (*d)[4], const uint32_t* Ah, const uint32_t* Al,
                                           const uint2* p, int ntBase) {
    uint2 B0 = __ldg(p + (ntBase + 0) * 32);
    uint2 B1 = __ldg(p + (ntBase + 1) * 32);
    uint2 B2 = __ldg(p + (ntBase + 2) * 32);
    uint2 B3 = __ldg(p + (ntBase + 3) * 32);
    mma_f16(d[ntBase + 0], Ah, B0.x, B0.y);
    mma_f16(d[ntBase + 1], Ah, B1.x, B1.y);
    mma_f16(d[ntBase + 2], Ah, B2.x, B2.y);
    mma_f16(d[ntBase + 3], Ah, B3.x, B3.y);
    mma_f16(d[ntBase + 0], Al, B0.x, B0.y);
    mma_f16(d[ntBase + 1], Al, B1.x, B1.y);
    mma_f16(d[ntBase + 2], Al, B2.x, B2.y);
    mma_f16(d[ntBase + 3], Al, B3.x, B3.y);
}
// single-product group (layer 1: A hi only)
__device__ __forceinline__ void mma_group4_1p(float (*d)[4], const uint32_t* Ah,
                                              const uint2* p, int ntBase) {
    uint2 B0 = __ldg(p + (ntBase + 0) * 32);
    uint2 B1 = __ldg(p + (ntBase + 1) * 32);
    uint2 B2 = __ldg(p + (ntBase + 2) * 32);
    uint2 B3 = __ldg(p + (ntBase + 3) * 32);
    mma_f16(d[ntBase + 0], Ah, B0.x, B0.y);
    mma_f16(d[ntBase + 1], Ah, B1.x, B1.y);
    mma_f16(d[ntBase + 2], Ah, B2.x, B2.y);
    mma_f16(d[ntBase + 3], Ah, B3.x, B3.y);
}

// ---------------- main kernel ----------------
__global__ void __launch_bounds__(TPB, 3) pinn_main(
    const float* __restrict__ coords, const float* __restrict__ fourierB,
    const float* __restrict__ b2g, const float* __restrict__ b3g,
    float* __restrict__ out)
{
    extern __shared__ __align__(16) unsigned char smem[];
    const uint32_t sb = smem_u32(smem);
    const int tid  = threadIdx.x;
    const int lane = tid & 31;
    const int warp = tid >> 5;        // 0..3, owns rows warp*16..warp*16+15

    float* sb2 = (float*)(smem + SM_B2);
    float* sb3 = (float*)(smem + SM_B3);
    sb2[tid] = b2g[tid];
    sb3[tid] = b3g[tid];

    // ================= warp-coalesced feature build (16 points per warp) ===========
    {
        const int m0w = blockIdx.x * PTS + warp * 16;
        // lanes 0..15 own per-point metadata
        float wa = 0.f, wb = 0.f, wc = 0.f, wd = 0.f, cx = 0.f, cy = 0.f, ct = 0.f;
        int i00 = 0, i01 = 0, i10 = 0, i11 = 0;
        if (lane < 16) {
            int m = m0w + lane;
            cx = coords[m * 3 + 0];
            cy = coords[m * 3 + 1];
            ct = coords[m * 3 + 2];
            int b = m >> 13;
            float fx = (cx + 1.f) * 0.5f * 63.f;
            float fy = (cy + 1.f) * 0.5f * 63.f;
            float x0f = floorf(fx), y0f = floorf(fy);
            int x0 = min(max((int)x0f, 0), 63);
            int x1 = max(min((int)x0f + 1, 63), 0);
            int y0 = min(max((int)y0f, 0), 63);
            int y1 = max(min((int)y0f + 1, 63), 0);
            wa = (x0f + 1.f - fx) * (y0f + 1.f - fy);
            wb = (x0f + 1.f - fx) * (fy - y0f);
            wc = (fx - x0f) * (y0f + 1.f - fy);
            wd = (fx - x0f) * (fy - y0f);
            // float2 index = row_index * 32
            i00 = (((((b << 6) + y0) << 6) + x0) << 5);
            i01 = (((((b << 6) + y1) << 6) + x0) << 5);
            i10 = (((((b << 6) + y0) << 6) + x1) << 5);
            i11 = (((((b << 6) + y1) << 6) + x1) << 5);
        }
        const float2* zt2 = (const float2*)g_zt;
        const uint32_t rowBase = SM_A + (uint32_t)(warp * 16) * SA_STRIDE;

        // gather: per point, 4 coalesced 256B corner loads; lane l -> channels 2l,2l+1
        #pragma unroll 4
        for (int i = 0; i < 16; i++) {
            float wwa = __shfl_sync(0xffffffffu, wa, i);
            float wwb = __shfl_sync(0xffffffffu, wb, i);
            float wwc = __shfl_sync(0xffffffffu, wc, i);
            float wwd = __shfl_sync(0xffffffffu, wd, i);
            int a00 = __shfl_sync(0xffffffffu, i00, i);
            int a01 = __shfl_sync(0xffffffffu, i01, i);
            int a10 = __shfl_sync(0xffffffffu, i10, i);
            int a11 = __shfl_sync(0xffffffffu, i11, i);
            float2 A = __ldg(zt2 + a00 + lane);
            float2 B = __ldg(zt2 + a01 + lane);
            float2 C = __ldg(zt2 + a10 + lane);
            float2 D = __ldg(zt2 + a11 + lane);
            float v0 = wwa * A.x + wwb * B.x + wwc * C.x + wwd * D.x;
            float v1 = wwa * A.y + wwb * B.y + wwc * C.y + wwd * D.y;
            *(uint32_t*)(smem + rowBase + i * SA_STRIDE + lane * 4) = packh2(v0, v1);
        }

        // fourier: lane l -> freqs 2l, 2l+1; sin cols 64..127, cos cols 128..191
        float f0 = __ldg(fourierB + 2 * lane)     * 2.0943951023931953f;
        float f1 = __ldg(fourierB + 2 * lane + 1) * 2.0943951023931953f;
        #pragma unroll 4
        for (int i = 0; i < 16; i++) {
            float t = __shfl_sync(0xffffffffu, ct, i);
            float s0, c0, s1, c1;
            fsincos(f0 * t, s0, c0);
            fsincos(f1 * t, s1, c1);
            *(uint32_t*)(smem + rowBase + i * SA_STRIDE + 128 + lane * 4) = packh2(s0, s1);
            *(uint32_t*)(smem + rowBase + i * SA_STRIDE + 256 + lane * 4) = packh2(c0, c1);
        }

        // tail cols 192..207 (+pad to 215): (cx,cy), (1,0), zeros
        #pragma unroll 4
        for (int i = 0; i < 16; i++) {
            float xcx = __shfl_sync(0xffffffffu, cx, i);
            float xcy = __shfl_sync(0xffffffffu, cy, i);
            if (lane < 12) {
                uint32_t w = 0;
                if (lane == 0)      w = packh2(xcx, xcy);
                else if (lane == 1) w = packh2(1.f, 0.f);
                *(uint32_t*)(smem + rowBase + i * SA_STRIDE + 384 + lane * 4) = w;
            }
        }
    }
    __syncthreads();   // sb2/sb3 ready (A is warp-private but barrier is cheap)

    // ldmatrix A address for this warp's 16 rows
    const uint32_t aAddr = sb + SM_A + (uint32_t)(warp * 16 + (lane & 15)) * SA_STRIDE + (lane >> 4) * 16;

    float d[16][4];

    // ================= layer 1 (A from smem, hi only) =================
    #pragma unroll
    for (int nt = 0; nt < 16; nt++)
        #pragma unroll
        for (int i = 0; i < 4; i++) d[nt][i] = 0.f;
    {
        const uint2* wf = g_wfrag + WF_L1 + lane;
        #pragma unroll 1
        for (int kt = 0; kt < L1_KT; kt++) {
            uint32_t Ah[4];
            ldsm4(Ah, aAddr + kt * 32);
            const uint2* p = wf + kt * 512;
            #pragma unroll
            for (int ng = 0; ng < 4; ng++)
                mma_group4_1p(d, Ah, p, 4 * ng);
        }
    }

    // epilogue 1 -> A2 in registers (bias folded into W1); D-frag == A-frag layout
    uint32_t A2h[8][4], A2l[8][4];
    #pragma unroll
    for (int kt = 0; kt < 8; kt++)
        #pragma unroll
        for (int j = 0; j < 4; j++) {
            int srcnt = 2 * kt + (j >> 1);
            int c = (j & 1) * 2;
            split2h(ftanh(d[srcnt][c]), ftanh(d[srcnt][c + 1]), A2h[kt][j], A2l[kt][j]);
        }

    // ================= layer 2 (A in registers) =================
    #pragma unroll
    for (int nt = 0; nt < 16; nt++)
        #pragma unroll
        for (int i = 0; i < 4; i++) d[nt][i] = 0.f;
    {
        const uint2* wf = g_wfrag + WF_L2 + lane;
        #pragma unroll 1
        for (int kt = 0; kt < L23_KT; kt++) {
            const uint2* p = wf + kt * 512;
            #pragma unroll
            for (int ng = 0; ng < 4; ng++)
                mma_group4(d, A2h[kt], A2l[kt], p, 4 * ng);
        }
    }

    // epilogue 2: +b2, tanh -> A3 (reuse A2 arrays)
    #pragma unroll
    for (int kt = 0; kt < 8; kt++)
        #pragma unroll
        for (int j = 0; j < 4; j++) {
            int srcnt = 2 * kt + (j >> 1);
            int c = (j & 1) * 2;
            int col = 8 * srcnt + (lane & 3) * 2;
            float2 bb = *(float2*)(sb2 + col);
            split2h(ftanh(d[srcnt][c] + bb.x), ftanh(d[srcnt][c + 1] + bb.y),
                    A2h[kt][j], A2l[kt][j]);
        }

    // ================= layer 3 (A in registers) =================
    #pragma unroll
    for (int nt = 0; nt < 16; nt++)
        #pragma unroll
        for (int i = 0; i < 4; i++) d[nt][i] = 0.f;
    {
        const uint2* wf = g_wfrag + WF_L3 + lane;
        #pragma unroll 1
        for (int kt = 0; kt < L23_KT; kt++) {
            const uint2* p = wf + kt * 512;
            #pragma unroll
            for (int ng = 0; ng < 4; ng++)
                mma_group4(d, A2h[kt], A2l[kt], p, 4 * ng);
        }
    }

    // epilogue 3: +b3, tanh -> A4 in registers (reuse A2 arrays)
    #pragma unroll
    for (int kt = 0; kt < 8; kt++)
        #pragma unroll
        for (int j = 0; j < 4; j++) {
            int srcnt = 2 * kt + (j >> 1);
            int c = (j & 1) * 2;
            int col = 8 * srcnt + (lane & 3) * 2;
            float2 bb = *(float2*)(sb3 + col);
            split2h(ftanh(d[srcnt][c] + bb.x), ftanh(d[srcnt][c + 1] + bb.y),
                    A2h[kt][j], A2l[kt][j]);
        }

    // ================= heads as MMA (N=8, 3 products) =================
    {
        float dh[4] = {0.f, 0.f, 0.f, 0.f};
        const uint4* hf = g_hfrag + lane;
        #pragma unroll
        for (int kt = 0; kt < 8; kt++) {
            uint4 HW = __ldg(hf + kt * 32);
            mma_f16(dh, A2h[kt], HW.x, HW.y);   // AhWh
            mma_f16(dh, A2l[kt], HW.x, HW.y);   // AlWh
            mma_f16(dh, A2h[kt], HW.z, HW.w);   // AhWl
        }
        int c0 = (lane & 3) * 2;
        int r0 = blockIdx.x * PTS + warp * 16 + (lane >> 2);
        float hb0 = g_hb[c0], hb1 = g_hb[c0 + 1];
        float a0 = dh[0] + hb0, a1 = dh[1] + hb1;
        float a2 = dh[2] + hb0, a3 = dh[3] + hb1;
        if (c0 == 6) {   // col 7 = softplus(.) + MIN_STD
            a1 = fmaxf(a1, 0.f) + log1pf(expf(-fabsf(a1))) + 0.01f;
            a3 = fmaxf(a3, 0.f) + log1pf(expf(-fabsf(a3))) + 0.01f;
        }
        *(float2*)(out + r0 * 8 + c0)       = make_float2(a0, a1);
        *(float2*)(out + (r0 + 8) * 8 + c0) = make_float2(a2, a3);
    }
}

// ---------------- host launch ----------------
extern "C" void kernel_launch(void* const* d_in, const int* in_sizes, int n_in,
                              void* d_out, int out_size) {
    const float* coords   = (const float*)d_in[0];
    const float* z_grid   = (const float*)d_in[1];
    const float* fourierB = (const float*)d_in[2];
    const float* W1   = (const float*)d_in[3];
    const float* b1   = (const float*)d_in[4];
    const float* W2   = (const float*)d_in[5];
    const float* b2   = (const float*)d_in[6];
    const float* W3   = (const float*)d_in[7];
    const float* b3   = (const float*)d_in[8];
    const float* Wvel = (const float*)d_in[9];
    const float* bvel = (const float*)d_in[10];
    const float* Wfh  = (const float*)d_in[11];
    const float* bfh  = (const float*)d_in[12];
    const float* Wph  = (const float*)d_in[13];
    const float* bph  = (const float*)d_in[14];
    const float* Wmu  = (const float*)d_in[15];
    const float* bmu  = (const float*)d_in[16];
    const float* Wstd = (const float*)d_in[17];
    const float* bstd = (const float*)d_in[18];
    float* out = (float*)d_out;

    static bool attr_set = false;
    if (!attr_set) {
        cudaFuncSetAttribute(pinn_main, cudaFuncAttributeMaxDynamicSharedMemorySize, SM_TOTAL);
        attr_set = true;
    }

    transpose_z_kernel<<<(16 * 64 * 64 * 64) / 256, 256>>>(z_grid);
    prep_wfrag_kernel<<<(WF_TOTAL + 255) / 256, 256>>>(W1, b1, W2, W3);
    prep_heads_kernel<<<1, 256>>>(Wvel, bvel, Wfh, bfh, Wph, bph, Wmu, bmu, Wstd, bstd);
    pinn_main<<<NBLK, TPB, SM_TOTAL>>>(coords, fourierB, b2, b3, out);
}

// round 12
// speedup vs baseline: 2.0356x; 1.2793x over previous
#include <cuda_runtime.h>
#include <cuda_fp16.h>
#include <math.h>
#include <stdint.h>

// ---------------- dims ----------------
#define NPTS 131072
#define PTS  64             // points per block
#define TPB  128            // 4 warps, each owns 16 points x full N=128
#define NBLK (NPTS/PTS)     // 2048
#define HID  128
#define L1_KT 13            // K = 208 (194 real + bias row + pad)
#define L23_KT 8            // K = 128

// ---------------- A smem layout (bytes) ----------------
#define SA_STRIDE 432       // feature row stride: 216 fp16 (16B-aligned)
#define SM_B2 0             // b2: 128 f32
#define SM_B3 512           // b3: 128 f32
#define SM_A  1024
#define SM_TOTAL (SM_A + 64*SA_STRIDE)   // 28672 -> 4 blocks/SM at <=128 regs

// weight fragment array (uint2 units): [layer][kt][nt 0..15][lane]  (fp16 hi only)
#define WF_L1 0
#define WF_L2 6656          // 13*512
#define WF_L3 10752
#define WF_TOTAL 14848

// ---------------- device scratch ----------------
__device__ float g_zt[16*64*64*64];          // z transposed (B,H,W,C)
__device__ uint2 g_wfrag[WF_TOTAL];          // MMA b-fragments {b0h,b1h} fp16
__device__ uint4 g_hfrag[8*32];              // head b-fragments {b0h,b1h,b0l,b1l}
__device__ float g_hb[8];                    // head biases

// ---------------- helpers ----------------
__device__ __forceinline__ uint32_t smem_u32(const void* p) {
    uint32_t a;
    asm("{ .reg .u64 t; cvta.to.shared.u64 t, %1; cvt.u32.u64 %0, t; }" : "=r"(a) : "l"(p));
    return a;
}
__device__ __forceinline__ void ldsm4(uint32_t* r, uint32_t a) {
    asm volatile("ldmatrix.sync.aligned.m8n8.x4.shared.b16 {%0,%1,%2,%3}, [%4];"
                 : "=r"(r[0]), "=r"(r[1]), "=r"(r[2]), "=r"(r[3]) : "r"(a));
}
__device__ __forceinline__ void mma_f16(float* d, const uint32_t* a, uint32_t b0, uint32_t b1) {
    asm volatile("mma.sync.aligned.m16n8k16.row.col.f32.f16.f16.f32 "
                 "{%0,%1,%2,%3}, {%4,%5,%6,%7}, {%8,%9}, {%0,%1,%2,%3};"
                 : "+f"(d[0]), "+f"(d[1]), "+f"(d[2]), "+f"(d[3])
                 : "r"(a[0]), "r"(a[1]), "r"(a[2]), "r"(a[3]), "r"(b0), "r"(b1));
}
// fast tanh: 1 - 2/(exp(2x)+1); ~1e-6 abs err
__device__ __forceinline__ float ftanh(float x) {
    float e = __expf(2.f * x);
    float r;
    asm("rcp.approx.f32 %0, %1;" : "=f"(r) : "f"(e + 1.f));
    return fmaf(-2.f, r, 1.f);
}
// pack (a,b) -> fp16x2 word, low half = a
__device__ __forceinline__ uint32_t packh2(float a, float b) {
    __half2 h = __floats2half2_rn(a, b);
    return *reinterpret_cast<uint32_t*>(&h);
}
// pack (a,b) fp32 pair -> hi fp16x2 word + lo (residual) fp16x2 word
__device__ __forceinline__ void split2h(float a, float b, uint32_t& hi, uint32_t& lo) {
    __half ah = __float2half_rn(a), bh = __float2half_rn(b);
    __half al = __float2half_rn(a - __half2float(ah));
    __half bl = __float2half_rn(b - __half2float(bh));
    hi = (uint32_t)__half_as_ushort(ah) | ((uint32_t)__half_as_ushort(bh) << 16);
    lo = (uint32_t)__half_as_ushort(al) | ((uint32_t)__half_as_ushort(bl) << 16);
}
// fast sin/cos with explicit 2-step 2*pi range reduction
__device__ __forceinline__ void fsincos(float x, float& s, float& c) {
    float k = rintf(x * 0.15915494309189535f);
    float r = fmaf(-k, 6.2831855f, x);
    r = fmaf(-k, -1.7484555e-7f, r);
    s = __sinf(r);
    c = __cosf(r);
}

// ---------------- prologue kernels ----------------
__global__ void __launch_bounds__(256) transpose_z_kernel(const float* __restrict__ z) {
    int i = blockIdx.x * 256 + threadIdx.x;
    int x = i & 63, y = (i >> 6) & 63, c = (i >> 12) & 63, b = i >> 18;
    g_zt[(((((b << 6) + y) << 6) + x) << 6) + c] = z[i];
}

// head weight for output col n, input k
__device__ __forceinline__ float head_w(int k, int n,
    const float* Wvel, const float* Wfh, const float* Wph,
    const float* Wmu, const float* Wstd)
{
    if (n < 2) return Wvel[k * 2 + n];
    if (n < 4) return Wfh[k * 2 + n - 2];
    if (n < 6) return Wph[k * 2 + n - 4];
    if (n == 6) return Wmu[k];
    return Wstd[k];
}

// Pre-pack trunk weights (fp16 hi) + head fragments (hi/lo) + head biases.
// Blocks 0..57 cover WF_TOTAL; the last block (58) does the heads.
__global__ void __launch_bounds__(256) prep_wfrag_kernel(
    const float* __restrict__ W1, const float* __restrict__ b1,
    const float* __restrict__ W2, const float* __restrict__ W3,
    const float* __restrict__ Wvel, const float* __restrict__ bvel,
    const float* __restrict__ Wfh,  const float* __restrict__ bfh,
    const float* __restrict__ Wph,  const float* __restrict__ bph,
    const float* __restrict__ Wmu,  const float* __restrict__ bmu,
    const float* __restrict__ Wstd, const float* __restrict__ bstd)
{
    int i = blockIdx.x * 256 + threadIdx.x;
    if (i < WF_TOTAL) {
        int layer, rem;
        const float* W;
        if (i < WF_L2)      { layer = 1; rem = i;          W = W1; }
        else if (i < WF_L3) { layer = 2; rem = i - WF_L2;  W = W2; }
        else                { layer = 3; rem = i - WF_L3;  W = W3; }
        int lane = rem & 31, nt = (rem >> 5) & 15, kt = rem >> 9;
        int n  = nt * 8 + (lane >> 2);
        int k0 = kt * 16 + (lane & 3) * 2;
        float v[4];
        #pragma unroll
        for (int j = 0; j < 4; j++) {
            int k = k0 + (j >> 1) * 8 + (j & 1);
            float val;
            if (layer == 1) {
                if (k < 194)       val = W[k * HID + n];
                else if (k == 194) val = b1[n];
                else               val = 0.f;
            } else {
                val = W[k * HID + n];
            }
            v[j] = val;
        }
        uint2 o;
        o.x = packh2(v[0], v[1]);
        o.y = packh2(v[2], v[3]);
        g_wfrag[i] = o;
    } else if (i >= WF_TOTAL && blockIdx.x == gridDim.x - 1 && threadIdx.x < 256 && i - WF_TOTAL < 256) {
        int t = i - WF_TOTAL;          // 0..255 = kt*32 + lane
        int lane = t & 31, kt = t >> 5;
        int n  = lane >> 2;
        int k0 = kt * 16 + (lane & 3) * 2;
        float v[4];
        #pragma unroll
        for (int j = 0; j < 4; j++) {
            int k = k0 + (j >> 1) * 8 + (j & 1);
            v[j] = head_w(k, n, Wvel, Wfh, Wph, Wmu, Wstd);
        }
        uint4 o;
        split2h(v[0], v[1], o.x, o.z);
        split2h(v[2], v[3], o.y, o.w);
        g_hfrag[t] = o;
        if (t < 8) {
            float hb;
            if      (t < 2)  hb = bvel[t];
            else if (t < 4)  hb = bfh[t - 2];
            else if (t < 6)  hb = bph[t - 4];
            else if (t == 6) hb = bmu[0];
            else             hb = bstd[0];
            g_hb[t] = hb;
        }
    }
}

// interleaved group of 4 n-tiles, single product (A hi only)
__device__ __forceinline__ void mma_group4_1p(float (*d)[4], const uint32_t* Ah,
                                              const uint2* p, int ntBase) {
    uint2 B0 = __ldg(p + (ntBase + 0) * 32);
    uint2 B1 = __ldg(p + (ntBase + 1) * 32);
    uint2 B2 = __ldg(p + (ntBase + 2) * 32);
    uint2 B3 = __ldg(p + (ntBase + 3) * 32);
    mma_f16(d[ntBase + 0], Ah, B0.x, B0.y);
    mma_f16(d[ntBase + 1], Ah, B1.x, B1.y);
    mma_f16(d[ntBase + 2], Ah, B2.x, B2.y);
    mma_f16(d[ntBase + 3], Ah, B3.x, B3.y);
}

// ---------------- main kernel ----------------
__global__ void __launch_bounds__(TPB, 4) pinn_main(
    const float* __restrict__ coords, const float* __restrict__ fourierB,
    const float* __restrict__ b2g, const float* __restrict__ b3g,
    float* __restrict__ out)
{
    extern __shared__ __align__(16) unsigned char smem[];
    const uint32_t sb = smem_u32(smem);
    const int tid  = threadIdx.x;
    const int lane = tid & 31;
    const int warp = tid >> 5;        // 0..3, owns rows warp*16..warp*16+15

    float* sb2 = (float*)(smem + SM_B2);
    float* sb3 = (float*)(smem + SM_B3);
    sb2[tid] = b2g[tid];
    sb3[tid] = b3g[tid];

    // ================= warp-coalesced feature build (16 points per warp) ===========
    {
        const int m0w = blockIdx.x * PTS + warp * 16;
        float wa = 0.f, wb = 0.f, wc = 0.f, wd = 0.f, cx = 0.f, cy = 0.f, ct = 0.f;
        int i00 = 0, i01 = 0, i10 = 0, i11 = 0;
        if (lane < 16) {
            int m = m0w + lane;
            cx = coords[m * 3 + 0];
            cy = coords[m * 3 + 1];
            ct = coords[m * 3 + 2];
            int b = m >> 13;
            float fx = (cx + 1.f) * 0.5f * 63.f;
            float fy = (cy + 1.f) * 0.5f * 63.f;
            float x0f = floorf(fx), y0f = floorf(fy);
            int x0 = min(max((int)x0f, 0), 63);
            int x1 = max(min((int)x0f + 1, 63), 0);
            int y0 = min(max((int)y0f, 0), 63);
            int y1 = max(min((int)y0f + 1, 63), 0);
            wa = (x0f + 1.f - fx) * (y0f + 1.f - fy);
            wb = (x0f + 1.f - fx) * (fy - y0f);
            wc = (fx - x0f) * (y0f + 1.f - fy);
            wd = (fx - x0f) * (fy - y0f);
            i00 = (((((b << 6) + y0) << 6) + x0) << 5);
            i01 = (((((b << 6) + y1) << 6) + x0) << 5);
            i10 = (((((b << 6) + y0) << 6) + x1) << 5);
            i11 = (((((b << 6) + y1) << 6) + x1) << 5);
        }
        const float2* zt2 = (const float2*)g_zt;
        const uint32_t rowBase = SM_A + (uint32_t)(warp * 16) * SA_STRIDE;

        #pragma unroll 4
        for (int i = 0; i < 16; i++) {
            float wwa = __shfl_sync(0xffffffffu, wa, i);
            float wwb = __shfl_sync(0xffffffffu, wb, i);
            float wwc = __shfl_sync(0xffffffffu, wc, i);
            float wwd = __shfl_sync(0xffffffffu, wd, i);
            int a00 = __shfl_sync(0xffffffffu, i00, i);
            int a01 = __shfl_sync(0xffffffffu, i01, i);
            int a10 = __shfl_sync(0xffffffffu, i10, i);
            int a11 = __shfl_sync(0xffffffffu, i11, i);
            float2 A = __ldg(zt2 + a00 + lane);
            float2 B = __ldg(zt2 + a01 + lane);
            float2 C = __ldg(zt2 + a10 + lane);
            float2 D = __ldg(zt2 + a11 + lane);
            float v0 = wwa * A.x + wwb * B.x + wwc * C.x + wwd * D.x;
            float v1 = wwa * A.y + wwb * B.y + wwc * C.y + wwd * D.y;
            *(uint32_t*)(smem + rowBase + i * SA_STRIDE + lane * 4) = packh2(v0, v1);
        }

        float f0 = __ldg(fourierB + 2 * lane)     * 2.0943951023931953f;
        float f1 = __ldg(fourierB + 2 * lane + 1) * 2.0943951023931953f;
        #pragma unroll 4
        for (int i = 0; i < 16; i++) {
            float t = __shfl_sync(0xffffffffu, ct, i);
            float s0, c0, s1, c1;
            fsincos(f0 * t, s0, c0);
            fsincos(f1 * t, s1, c1);
            *(uint32_t*)(smem + rowBase + i * SA_STRIDE + 128 + lane * 4) = packh2(s0, s1);
            *(uint32_t*)(smem + rowBase + i * SA_STRIDE + 256 + lane * 4) = packh2(c0, c1);
        }

        #pragma unroll 4
        for (int i = 0; i < 16; i++) {
            float xcx = __shfl_sync(0xffffffffu, cx, i);
            float xcy = __shfl_sync(0xffffffffu, cy, i);
            if (lane < 12) {
                uint32_t w = 0;
                if (lane == 0)      w = packh2(xcx, xcy);
                else if (lane == 1) w = packh2(1.f, 0.f);
                *(uint32_t*)(smem + rowBase + i * SA_STRIDE + 384 + lane * 4) = w;
            }
        }
    }
    __syncthreads();   // sb2/sb3 ready

    // ldmatrix A address for this warp's 16 rows
    const uint32_t aAddr = sb + SM_A + (uint32_t)(warp * 16 + (lane & 15)) * SA_STRIDE + (lane >> 4) * 16;

    float d[16][4];

    // ================= layer 1 (A from smem, hi only) =================
    #pragma unroll
    for (int nt = 0; nt < 16; nt++)
        #pragma unroll
        for (int i = 0; i < 4; i++) d[nt][i] = 0.f;
    {
        const uint2* wf = g_wfrag + WF_L1 + lane;
        #pragma unroll 1
        for (int kt = 0; kt < L1_KT; kt++) {
            uint32_t Ah[4];
            ldsm4(Ah, aAddr + kt * 32);
            const uint2* p = wf + kt * 512;
            #pragma unroll
            for (int ng = 0; ng < 4; ng++)
                mma_group4_1p(d, Ah, p, 4 * ng);
        }
    }

    // epilogue 1 -> A2 (fp16, hi only) in registers; D-frag == A-frag layout
    uint32_t A2h[8][4];
    #pragma unroll
    for (int kt = 0; kt < 8; kt++)
        #pragma unroll
        for (int j = 0; j < 4; j++) {
            int srcnt = 2 * kt + (j >> 1);
            int c = (j & 1) * 2;
            A2h[kt][j] = packh2(ftanh(d[srcnt][c]), ftanh(d[srcnt][c + 1]));
        }

    // ================= layer 2 (A in registers) =================
    #pragma unroll
    for (int nt = 0; nt < 16; nt++)
        #pragma unroll
        for (int i = 0; i < 4; i++) d[nt][i] = 0.f;
    {
        const uint2* wf = g_wfrag + WF_L2 + lane;
        #pragma unroll 1
        for (int kt = 0; kt < L23_KT; kt++) {
            const uint2* p = wf + kt * 512;
            #pragma unroll
            for (int ng = 0; ng < 4; ng++)
                mma_group4_1p(d, A2h[kt], p, 4 * ng);
        }
    }

    // epilogue 2: +b2, tanh -> A3 (reuse A2h)
    #pragma unroll
    for (int kt = 0; kt < 8; kt++)
        #pragma unroll
        for (int j = 0; j < 4; j++) {
            int srcnt = 2 * kt + (j >> 1);
            int c = (j & 1) * 2;
            int col = 8 * srcnt + (lane & 3) * 2;
            float2 bb = *(float2*)(sb2 + col);
            A2h[kt][j] = packh2(ftanh(d[srcnt][c] + bb.x), ftanh(d[srcnt][c + 1] + bb.y));
        }

    // ================= layer 3 (A in registers) =================
    #pragma unroll
    for (int nt = 0; nt < 16; nt++)
        #pragma unroll
        for (int i = 0; i < 4; i++) d[nt][i] = 0.f;
    {
        const uint2* wf = g_wfrag + WF_L3 + lane;
        #pragma unroll 1
        for (int kt = 0; kt < L23_KT; kt++) {
            const uint2* p = wf + kt * 512;
            #pragma unroll
            for (int ng = 0; ng < 4; ng++)
                mma_group4_1p(d, A2h[kt], p, 4 * ng);
        }
    }

    // epilogue 3: +b3, tanh -> A4 (reuse A2h)
    #pragma unroll
    for (int kt = 0; kt < 8; kt++)
        #pragma unroll
        for (int j = 0; j < 4; j++) {
            int srcnt = 2 * kt + (j >> 1);
            int c = (j & 1) * 2;
            int col = 8 * srcnt + (lane & 3) * 2;
            float2 bb = *(float2*)(sb3 + col);
            A2h[kt][j] = packh2(ftanh(d[srcnt][c] + bb.x), ftanh(d[srcnt][c + 1] + bb.y));
        }

    // ================= heads as MMA (N=8; W hi+lo, A hi) =================
    {
        float dh[4] = {0.f, 0.f, 0.f, 0.f};
        const uint4* hf = g_hfrag + lane;
        #pragma unroll
        for (int kt = 0; kt < 8; kt++) {
            uint4 HW = __ldg(hf + kt * 32);
            mma_f16(dh, A2h[kt], HW.x, HW.y);   // AhWh
            mma_f16(dh, A2h[kt], HW.z, HW.w);   // AhWl
        }
        int c0 = (lane & 3) * 2;
        int r0 = blockIdx.x * PTS + warp * 16 + (lane >> 2);
        float hb0 = g_hb[c0], hb1 = g_hb[c0 + 1];
        float a0 = dh[0] + hb0, a1 = dh[1] + hb1;
        float a2 = dh[2] + hb0, a3 = dh[3] + hb1;
        if (c0 == 6) {   // col 7 = softplus(.) + MIN_STD
            a1 = fmaxf(a1, 0.f) + log1pf(expf(-fabsf(a1))) + 0.01f;
            a3 = fmaxf(a3, 0.f) + log1pf(expf(-fabsf(a3))) + 0.01f;
        }
        *(float2*)(out + r0 * 8 + c0)       = make_float2(a0, a1);
        *(float2*)(out + (r0 + 8) * 8 + c0) = make_float2(a2, a3);
    }
}

// ---------------- host launch ----------------
extern "C" void kernel_launch(void* const* d_in, const int* in_sizes, int n_in,
                              void* d_out, int out_size) {
    const float* coords   = (const float*)d_in[0];
    const float* z_grid   = (const float*)d_in[1];
    const float* fourierB = (const float*)d_in[2];
    const float* W1   = (const float*)d_in[3];
    const float* b1   = (const float*)d_in[4];
    const float* W2   = (const float*)d_in[5];
    const float* b2   = (const float*)d_in[6];
    const float* W3   = (const float*)d_in[7];
    const float* b3   = (const float*)d_in[8];
    const float* Wvel = (const float*)d_in[9];
    const float* bvel = (const float*)d_in[10];
    const float* Wfh  = (const float*)d_in[11];
    const float* bfh  = (const float*)d_in[12];
    const float* Wph  = (const float*)d_in[13];
    const float* bph  = (const float*)d_in[14];
    const float* Wmu  = (const float*)d_in[15];
    const float* bmu  = (const float*)d_in[16];
    const float* Wstd = (const float*)d_in[17];
    const float* bstd = (const float*)d_in[18];
    float* out = (float*)d_out;

    static bool attr_set = false;
    if (!attr_set) {
        cudaFuncSetAttribute(pinn_main, cudaFuncAttributeMaxDynamicSharedMemorySize, SM_TOTAL);
        attr_set = true;
    }

    transpose_z_kernel<<<(16 * 64 * 64 * 64) / 256, 256>>>(z_grid);
    // trunk fragments + heads folded into one kernel (extra tail block does heads)
    prep_wfrag_kernel<<<(WF_TOTAL + 255) / 256 + 1, 256>>>(
        W1, b1, W2, W3,
        Wvel, bvel, Wfh, bfh, Wph, bph, Wmu, bmu, Wstd, bstd);
    pinn_main<<<NBLK, TPB, SM_TOTAL>>>(coords, fourierB, b2, b3, out);
}

// round 13
// speedup vs baseline: 2.6313x; 1.2926x over previous
#include <cuda_runtime.h>
#include <cuda_fp16.h>
#include <math.h>
#include <stdint.h>

// ---------------- dims ----------------
#define NPTS 131072
#define PTS  64             // points per block
#define TPB  128            // 4 warps, each owns 16 points x full N=128
#define NBLK (NPTS/PTS)     // 2048
#define HID  128
#define L1_KT 13            // K = 208 (194 real + bias row + pad)
#define L23_KT 8            // K = 128

// ---------------- A smem layout (bytes) ----------------
#define SA_STRIDE 432       // feature row stride: 216 fp16 (16B-aligned)
#define SM_B2 0             // b2: 128 f32
#define SM_B3 512           // b3: 128 f32
#define SM_A  1024
#define SM_TOTAL (SM_A + 64*SA_STRIDE)   // 28672 -> 4 blocks/SM at <=128 regs

// weight fragment array (uint2 units): [layer][kt][nt 0..15][lane]  (fp16 hi only)
#define WF_L1 0
#define WF_L2 6656          // 13*512
#define WF_L3 10752
#define WF_TOTAL 14848

// ---------------- device scratch ----------------
__device__ uint32_t g_zt16[16*64*64*32];     // z transposed (B,H,W,C/2) packed half2
__device__ uint2 g_wfrag[WF_TOTAL];          // MMA b-fragments {b0h,b1h} fp16
__device__ uint4 g_hfrag[8*32];              // head b-fragments {b0h,b1h,b0l,b1l}
__device__ float g_hb[8];                    // head biases

// ---------------- helpers ----------------
__device__ __forceinline__ uint32_t smem_u32(const void* p) {
    uint32_t a;
    asm("{ .reg .u64 t; cvta.to.shared.u64 t, %1; cvt.u32.u64 %0, t; }" : "=r"(a) : "l"(p));
    return a;
}
__device__ __forceinline__ void ldsm4(uint32_t* r, uint32_t a) {
    asm volatile("ldmatrix.sync.aligned.m8n8.x4.shared.b16 {%0,%1,%2,%3}, [%4];"
                 : "=r"(r[0]), "=r"(r[1]), "=r"(r[2]), "=r"(r[3]) : "r"(a));
}
__device__ __forceinline__ void mma_f16(float* d, const uint32_t* a, uint32_t b0, uint32_t b1) {
    asm volatile("mma.sync.aligned.m16n8k16.row.col.f32.f16.f16.f32 "
                 "{%0,%1,%2,%3}, {%4,%5,%6,%7}, {%8,%9}, {%0,%1,%2,%3};"
                 : "+f"(d[0]), "+f"(d[1]), "+f"(d[2]), "+f"(d[3])
                 : "r"(a[0]), "r"(a[1]), "r"(a[2]), "r"(a[3]), "r"(b0), "r"(b1));
}
// fast tanh: 1 - 2/(exp(2x)+1); ~1e-6 abs err
__device__ __forceinline__ float ftanh(float x) {
    float e = __expf(2.f * x);
    float r;
    asm("rcp.approx.f32 %0, %1;" : "=f"(r) : "f"(e + 1.f));
    return fmaf(-2.f, r, 1.f);
}
// pack (a,b) -> fp16x2 word, low half = a
__device__ __forceinline__ uint32_t packh2(float a, float b) {
    __half2 h = __floats2half2_rn(a, b);
    return *reinterpret_cast<uint32_t*>(&h);
}
// pack (a,b) fp32 pair -> hi fp16x2 word + lo (residual) fp16x2 word
__device__ __forceinline__ void split2h(float a, float b, uint32_t& hi, uint32_t& lo) {
    __half ah = __float2half_rn(a), bh = __float2half_rn(b);
    __half al = __float2half_rn(a - __half2float(ah));
    __half bl = __float2half_rn(b - __half2float(bh));
    hi = (uint32_t)__half_as_ushort(ah) | ((uint32_t)__half_as_ushort(bh) << 16);
    lo = (uint32_t)__half_as_ushort(al) | ((uint32_t)__half_as_ushort(bl) << 16);
}
// fast sin/cos with explicit 2-step 2*pi range reduction
__device__ __forceinline__ void fsincos(float x, float& s, float& c) {
    float k = rintf(x * 0.15915494309189535f);
    float r = fmaf(-k, 6.2831855f, x);
    r = fmaf(-k, -1.7484555e-7f, r);
    s = __sinf(r);
    c = __cosf(r);
}

// ---------------- prologue kernels ----------------
// Tiled transpose (B,C,H,W) fp32 -> (B,H,W,C/2) packed half2.
// One block per (b,y): transposes a 64(c) x 64(x) tile via smem, fully coalesced.
__global__ void __launch_bounds__(256) transpose_z_kernel(const float* __restrict__ z) {
    __shared__ uint32_t tile[64][33];     // [x][cpair], pad 33 -> conflict-free both phases
    const int by = blockIdx.x;            // b*64 + y
    const int b = by >> 6, y = by & 63;
    const int tx = threadIdx.x & 63, ty = threadIdx.x >> 6;   // ty: 0..3
    const float* src = z + ((b << 6) << 12) + (y << 6);       // + c*4096 + x

    #pragma unroll
    for (int j = 0; j < 8; j++) {
        int cp = j * 4 + ty;              // channel pair 0..31
        float v0 = __ldg(src + (2 * cp)     * 4096 + tx);
        float v1 = __ldg(src + (2 * cp + 1) * 4096 + tx);
        tile[tx][cp] = packh2(v0, v1);
    }
    __syncthreads();

    const int lane = threadIdx.x & 31, w = threadIdx.x >> 5;  // w: 0..7
    uint32_t* dst = g_zt16 + ((uint32_t)by << 11);            // + x*32 + cpair
    #pragma unroll
    for (int j = 0; j < 8; j++) {
        int x = w * 8 + j;
        dst[(x << 5) + lane] = tile[x][lane];
    }
}

// head weight for output col n, input k
__device__ __forceinline__ float head_w(int k, int n,
    const float* Wvel, const float* Wfh, const float* Wph,
    const float* Wmu, const float* Wstd)
{
    if (n < 2) return Wvel[k * 2 + n];
    if (n < 4) return Wfh[k * 2 + n - 2];
    if (n < 6) return Wph[k * 2 + n - 4];
    if (n == 6) return Wmu[k];
    return Wstd[k];
}

// Pre-pack trunk weights (fp16 hi) + head fragments (hi/lo) + head biases.
__global__ void __launch_bounds__(256) prep_wfrag_kernel(
    const float* __restrict__ W1, const float* __restrict__ b1,
    const float* __restrict__ W2, const float* __restrict__ W3,
    const float* __restrict__ Wvel, const float* __restrict__ bvel,
    const float* __restrict__ Wfh,  const float* __restrict__ bfh,
    const float* __restrict__ Wph,  const float* __restrict__ bph,
    const float* __restrict__ Wmu,  const float* __restrict__ bmu,
    const float* __restrict__ Wstd, const float* __restrict__ bstd)
{
    int i = blockIdx.x * 256 + threadIdx.x;
    if (i < WF_TOTAL) {
        int layer, rem;
        const float* W;
        if (i < WF_L2)      { layer = 1; rem = i;          W = W1; }
        else if (i < WF_L3) { layer = 2; rem = i - WF_L2;  W = W2; }
        else                { layer = 3; rem = i - WF_L3;  W = W3; }
        int lane = rem & 31, nt = (rem >> 5) & 15, kt = rem >> 9;
        int n  = nt * 8 + (lane >> 2);
        int k0 = kt * 16 + (lane & 3) * 2;
        float v[4];
        #pragma unroll
        for (int j = 0; j < 4; j++) {
            int k = k0 + (j >> 1) * 8 + (j & 1);
            float val;
            if (layer == 1) {
                if (k < 194)       val = W[k * HID + n];
                else if (k == 194) val = b1[n];
                else               val = 0.f;
            } else {
                val = W[k * HID + n];
            }
            v[j] = val;
        }
        uint2 o;
        o.x = packh2(v[0], v[1]);
        o.y = packh2(v[2], v[3]);
        g_wfrag[i] = o;
    } else if (blockIdx.x == gridDim.x - 1 && i - WF_TOTAL < 256) {
        int t = i - WF_TOTAL;          // 0..255 = kt*32 + lane
        int lane = t & 31, kt = t >> 5;
        int n  = lane >> 2;
        int k0 = kt * 16 + (lane & 3) * 2;
        float v[4];
        #pragma unroll
        for (int j = 0; j < 4; j++) {
            int k = k0 + (j >> 1) * 8 + (j & 1);
            v[j] = head_w(k, n, Wvel, Wfh, Wph, Wmu, Wstd);
        }
        uint4 o;
        split2h(v[0], v[1], o.x, o.z);
        split2h(v[2], v[3], o.y, o.w);
        g_hfrag[t] = o;
        if (t < 8) {
            float hb;
            if      (t < 2)  hb = bvel[t];
            else if (t < 4)  hb = bfh[t - 2];
            else if (t < 6)  hb = bph[t - 4];
            else if (t == 6) hb = bmu[0];
            else             hb = bstd[0];
            g_hb[t] = hb;
        }
    }
}

// interleaved group of 4 n-tiles, single product (A hi only)
__device__ __forceinline__ void mma_group4_1p(float (*d)[4], const uint32_t* Ah,
                                              const uint2* p, int ntBase) {
    uint2 B0 = __ldg(p + (ntBase + 0) * 32);
    uint2 B1 = __ldg(p + (ntBase + 1) * 32);
    uint2 B2 = __ldg(p + (ntBase + 2) * 32);
    uint2 B3 = __ldg(p + (ntBase + 3) * 32);
    mma_f16(d[ntBase + 0], Ah, B0.x, B0.y);
    mma_f16(d[ntBase + 1], Ah, B1.x, B1.y);
    mma_f16(d[ntBase + 2], Ah, B2.x, B2.y);
    mma_f16(d[ntBase + 3], Ah, B3.x, B3.y);
}

// ---------------- main kernel ----------------
__global__ void __launch_bounds__(TPB, 4) pinn_main(
    const float* __restrict__ coords, const float* __restrict__ fourierB,
    const float* __restrict__ b2g, const float* __restrict__ b3g,
    float* __restrict__ out)
{
    extern __shared__ __align__(16) unsigned char smem[];
    const uint32_t sb = smem_u32(smem);
    const int tid  = threadIdx.x;
    const int lane = tid & 31;
    const int warp = tid >> 5;        // 0..3, owns rows warp*16..warp*16+15

    float* sb2 = (float*)(smem + SM_B2);
    float* sb3 = (float*)(smem + SM_B3);
    sb2[tid] = b2g[tid];
    sb3[tid] = b3g[tid];

    // ================= warp-coalesced feature build (16 points per warp) ===========
    {
        const int m0w = blockIdx.x * PTS + warp * 16;
        float wa = 0.f, wb = 0.f, wc = 0.f, wd = 0.f, cx = 0.f, cy = 0.f, ct = 0.f;
        int i00 = 0, i01 = 0, i10 = 0, i11 = 0;
        if (lane < 16) {
            int m = m0w + lane;
            cx = coords[m * 3 + 0];
            cy = coords[m * 3 + 1];
            ct = coords[m * 3 + 2];
            int b = m >> 13;
            float fx = (cx + 1.f) * 0.5f * 63.f;
            float fy = (cy + 1.f) * 0.5f * 63.f;
            float x0f = floorf(fx), y0f = floorf(fy);
            int x0 = min(max((int)x0f, 0), 63);
            int x1 = max(min((int)x0f + 1, 63), 0);
            int y0 = min(max((int)y0f, 0), 63);
            int y1 = max(min((int)y0f + 1, 63), 0);
            wa = (x0f + 1.f - fx) * (y0f + 1.f - fy);
            wb = (x0f + 1.f - fx) * (fy - y0f);
            wc = (fx - x0f) * (y0f + 1.f - fy);
            wd = (fx - x0f) * (fy - y0f);
            i00 = (((((b << 6) + y0) << 6) + x0) << 5);   // uint32 row base
            i01 = (((((b << 6) + y1) << 6) + x0) << 5);
            i10 = (((((b << 6) + y0) << 6) + x1) << 5);
            i11 = (((((b << 6) + y1) << 6) + x1) << 5);
        }
        const uint32_t* zt = g_zt16;
        const uint32_t rowBase = SM_A + (uint32_t)(warp * 16) * SA_STRIDE;

        #pragma unroll 4
        for (int i = 0; i < 16; i++) {
            float wwa = __shfl_sync(0xffffffffu, wa, i);
            float wwb = __shfl_sync(0xffffffffu, wb, i);
            float wwc = __shfl_sync(0xffffffffu, wc, i);
            float wwd = __shfl_sync(0xffffffffu, wd, i);
            int a00 = __shfl_sync(0xffffffffu, i00, i);
            int a01 = __shfl_sync(0xffffffffu, i01, i);
            int a10 = __shfl_sync(0xffffffffu, i10, i);
            int a11 = __shfl_sync(0xffffffffu, i11, i);
            uint32_t wA = __ldg(zt + a00 + lane);
            uint32_t wB = __ldg(zt + a01 + lane);
            uint32_t wC = __ldg(zt + a10 + lane);
            uint32_t wD = __ldg(zt + a11 + lane);
            float2 A = __half22float2(*reinterpret_cast<__half2*>(&wA));
            float2 B = __half22float2(*reinterpret_cast<__half2*>(&wB));
            float2 C = __half22float2(*reinterpret_cast<__half2*>(&wC));
            float2 D = __half22float2(*reinterpret_cast<__half2*>(&wD));
            float v0 = wwa * A.x + wwb * B.x + wwc * C.x + wwd * D.x;
            float v1 = wwa * A.y + wwb * B.y + wwc * C.y + wwd * D.y;
            *(uint32_t*)(smem + rowBase + i * SA_STRIDE + lane * 4) = packh2(v0, v1);
        }

        float f0 = __ldg(fourierB + 2 * lane)     * 2.0943951023931953f;
        float f1 = __ldg(fourierB + 2 * lane + 1) * 2.0943951023931953f;
        #pragma unroll 4
        for (int i = 0; i < 16; i++) {
            float t = __shfl_sync(0xffffffffu, ct, i);
            float s0, c0, s1, c1;
            fsincos(f0 * t, s0, c0);
            fsincos(f1 * t, s1, c1);
            *(uint32_t*)(smem + rowBase + i * SA_STRIDE + 128 + lane * 4) = packh2(s0, s1);
            *(uint32_t*)(smem + rowBase + i * SA_STRIDE + 256 + lane * 4) = packh2(c0, c1);
        }

        #pragma unroll 4
        for (int i = 0; i < 16; i++) {
            float xcx = __shfl_sync(0xffffffffu, cx, i);
            float xcy = __shfl_sync(0xffffffffu, cy, i);
            if (lane < 12) {
                uint32_t w = 0;
                if (lane == 0)      w = packh2(xcx, xcy);
                else if (lane == 1) w = packh2(1.f, 0.f);
                *(uint32_t*)(smem + rowBase + i * SA_STRIDE + 384 + lane * 4) = w;
            }
        }
    }
    __syncthreads();   // sb2/sb3 ready

    // ldmatrix A address for this warp's 16 rows
    const uint32_t aAddr = sb + SM_A + (uint32_t)(warp * 16 + (lane & 15)) * SA_STRIDE + (lane >> 4) * 16;

    float d[16][4];

    // ================= layer 1 (A from smem, hi only) =================
    #pragma unroll
    for (int nt = 0; nt < 16; nt++)
        #pragma unroll
        for (int i = 0; i < 4; i++) d[nt][i] = 0.f;
    {
        const uint2* wf = g_wfrag + WF_L1 + lane;
        #pragma unroll 1
        for (int kt = 0; kt < L1_KT; kt++) {
            uint32_t Ah[4];
            ldsm4(Ah, aAddr + kt * 32);
            const uint2* p = wf + kt * 512;
            #pragma unroll
            for (int ng = 0; ng < 4; ng++)
                mma_group4_1p(d, Ah, p, 4 * ng);
        }
    }

    // epilogue 1 -> A2 (fp16, hi only) in registers; D-frag == A-frag layout
    uint32_t A2h[8][4];
    #pragma unroll
    for (int kt = 0; kt < 8; kt++)
        #pragma unroll
        for (int j = 0; j < 4; j++) {
            int srcnt = 2 * kt + (j >> 1);
            int c = (j & 1) * 2;
            A2h[kt][j] = packh2(ftanh(d[srcnt][c]), ftanh(d[srcnt][c + 1]));
        }

    // ================= layer 2 (A in registers) =================
    #pragma unroll
    for (int nt = 0; nt < 16; nt++)
        #pragma unroll
        for (int i = 0; i < 4; i++) d[nt][i] = 0.f;
    {
        const uint2* wf = g_wfrag + WF_L2 + lane;
        #pragma unroll 1
        for (int kt = 0; kt < L23_KT; kt++) {
            const uint2* p = wf + kt * 512;
            #pragma unroll
            for (int ng = 0; ng < 4; ng++)
                mma_group4_1p(d, A2h[kt], p, 4 * ng);
        }
    }

    // epilogue 2: +b2, tanh -> A3 (reuse A2h)
    #pragma unroll
    for (int kt = 0; kt < 8; kt++)
        #pragma unroll
        for (int j = 0; j < 4; j++) {
            int srcnt = 2 * kt + (j >> 1);
            int c = (j & 1) * 2;
            int col = 8 * srcnt + (lane & 3) * 2;
            float2 bb = *(float2*)(sb2 + col);
            A2h[kt][j] = packh2(ftanh(d[srcnt][c] + bb.x), ftanh(d[srcnt][c + 1] + bb.y));
        }

    // ================= layer 3 (A in registers) =================
    #pragma unroll
    for (int nt = 0; nt < 16; nt++)
        #pragma unroll
        for (int i = 0; i < 4; i++) d[nt][i] = 0.f;
    {
        const uint2* wf = g_wfrag + WF_L3 + lane;
        #pragma unroll 1
        for (int kt = 0; kt < L23_KT; kt++) {
            const uint2* p = wf + kt * 512;
            #pragma unroll
            for (int ng = 0; ng < 4; ng++)
                mma_group4_1p(d, A2h[kt], p, 4 * ng);
        }
    }

    // epilogue 3: +b3, tanh -> A4 (reuse A2h)
    #pragma unroll
    for (int kt = 0; kt < 8; kt++)
        #pragma unroll
        for (int j = 0; j < 4; j++) {
            int srcnt = 2 * kt + (j >> 1);
            int c = (j & 1) * 2;
            int col = 8 * srcnt + (lane & 3) * 2;
            float2 bb = *(float2*)(sb3 + col);
            A2h[kt][j] = packh2(ftanh(d[srcnt][c] + bb.x), ftanh(d[srcnt][c + 1] + bb.y));
        }

    // ================= heads as MMA (N=8; W hi+lo, A hi) =================
    {
        float dh[4] = {0.f, 0.f, 0.f, 0.f};
        const uint4* hf = g_hfrag + lane;
        #pragma unroll
        for (int kt = 0; kt < 8; kt++) {
            uint4 HW = __ldg(hf + kt * 32);
            mma_f16(dh, A2h[kt], HW.x, HW.y);   // AhWh
            mma_f16(dh, A2h[kt], HW.z, HW.w);   // AhWl
        }
        int c0 = (lane & 3) * 2;
        int r0 = blockIdx.x * PTS + warp * 16 + (lane >> 2);
        float hb0 = g_hb[c0], hb1 = g_hb[c0 + 1];
        float a0 = dh[0] + hb0, a1 = dh[1] + hb1;
        float a2 = dh[2] + hb0, a3 = dh[3] + hb1;
        if (c0 == 6) {   // col 7 = softplus(.) + MIN_STD
            a1 = fmaxf(a1, 0.f) + log1pf(expf(-fabsf(a1))) + 0.01f;
            a3 = fmaxf(a3, 0.f) + log1pf(expf(-fabsf(a3))) + 0.01f;
        }
        *(float2*)(out + r0 * 8 + c0)       = make_float2(a0, a1);
        *(float2*)(out + (r0 + 8) * 8 + c0) = make_float2(a2, a3);
    }
}

// ---------------- host launch ----------------
extern "C" void kernel_launch(void* const* d_in, const int* in_sizes, int n_in,
                              void* d_out, int out_size) {
    const float* coords   = (const float*)d_in[0];
    const float* z_grid   = (const float*)d_in[1];
    const float* fourierB = (const float*)d_in[2];
    const float* W1   = (const float*)d_in[3];
    const float* b1   = (const float*)d_in[4];
    const float* W2   = (const float*)d_in[5];
    const float* b2   = (const float*)d_in[6];
    const float* W3   = (const float*)d_in[7];
    const float* b3   = (const float*)d_in[8];
    const float* Wvel = (const float*)d_in[9];
    const float* bvel = (const float*)d_in[10];
    const float* Wfh  = (const float*)d_in[11];
    const float* bfh  = (const float*)d_in[12];
    const float* Wph  = (const float*)d_in[13];
    const float* bph  = (const float*)d_in[14];
    const float* Wmu  = (const float*)d_in[15];
    const float* bmu  = (const float*)d_in[16];
    const float* Wstd = (const float*)d_in[17];
    const float* bstd = (const float*)d_in[18];
    float* out = (float*)d_out;

    static bool attr_set = false;
    if (!attr_set) {
        cudaFuncSetAttribute(pinn_main, cudaFuncAttributeMaxDynamicSharedMemorySize, SM_TOTAL);
        attr_set = true;
    }

    transpose_z_kernel<<<16 * 64, 256>>>(z_grid);
    prep_wfrag_kernel<<<(WF_TOTAL + 255) / 256 + 1, 256>>>(
        W1, b1, W2, W3,
        Wvel, bvel, Wfh, bfh, Wph, bph, Wmu, bmu, Wstd, bstd);
    pinn_main<<<NBLK, TPB, SM_TOTAL>>>(coords, fourierB, b2, b3, out);
}

// round 14
// speedup vs baseline: 2.6411x; 1.0037x over previous
#include <cuda_runtime.h>
#include <cuda_fp16.h>
#include <math.h>
#include <stdint.h>

// ---------------- dims ----------------
#define NPTS 131072
#define PTS  64             // points per block
#define TPB  128            // 4 warps, each owns 16 points x full N=128
#define NBLK (NPTS/PTS)     // 2048
#define HID  128
#define L1_KT 13            // K = 208 (194 real + bias row + pad)
#define L23_KT 8            // K = 128

// ---------------- A smem layout (bytes) ----------------
#define SA_STRIDE 432       // feature row stride: 216 fp16 (16B-aligned)
#define SM_B2 0             // b2: 128 f32
#define SM_B3 512           // b3: 128 f32
#define SM_A  1024
#define SM_TOTAL (SM_A + 64*SA_STRIDE)   // 28672 -> 4 blocks/SM at <=128 regs

// weight fragment array (uint2 units): [layer][kt][nt 0..15][lane]  (fp16 hi only)
#define WF_L1 0
#define WF_L2 6656          // 13*512
#define WF_L3 10752
#define WF_TOTAL 14848      // = 58 * 256 exactly

// prologue grid split
#define PRO_TRANS 1024      // transpose blocks (b*64+y)
#define PRO_FRAG  58        // trunk fragment blocks
#define PRO_TOTAL (PRO_TRANS + PRO_FRAG + 1)

// ---------------- device scratch ----------------
__device__ uint32_t g_zt16[16*64*64*32];     // z transposed (B,H,W,C/2) packed half2
__device__ uint2 g_wfrag[WF_TOTAL];          // MMA b-fragments {b0h,b1h} fp16
__device__ uint4 g_hfrag[8*32];              // head b-fragments {b0h,b1h,b0l,b1l}
__device__ float g_hb[8];                    // head biases

// ---------------- helpers ----------------
__device__ __forceinline__ uint32_t smem_u32(const void* p) {
    uint32_t a;
    asm("{ .reg .u64 t; cvta.to.shared.u64 t, %1; cvt.u32.u64 %0, t; }" : "=r"(a) : "l"(p));
    return a;
}
__device__ __forceinline__ void ldsm4(uint32_t* r, uint32_t a) {
    asm volatile("ldmatrix.sync.aligned.m8n8.x4.shared.b16 {%0,%1,%2,%3}, [%4];"
                 : "=r"(r[0]), "=r"(r[1]), "=r"(r[2]), "=r"(r[3]) : "r"(a));
}
__device__ __forceinline__ void mma_f16(float* d, const uint32_t* a, uint32_t b0, uint32_t b1) {
    asm volatile("mma.sync.aligned.m16n8k16.row.col.f32.f16.f16.f32 "
                 "{%0,%1,%2,%3}, {%4,%5,%6,%7}, {%8,%9}, {%0,%1,%2,%3};"
                 : "+f"(d[0]), "+f"(d[1]), "+f"(d[2]), "+f"(d[3])
                 : "r"(a[0]), "r"(a[1]), "r"(a[2]), "r"(a[3]), "r"(b0), "r"(b1));
}
// fast tanh: 1 - 2/(exp(2x)+1); ~1e-6 abs err
__device__ __forceinline__ float ftanh(float x) {
    float e = __expf(2.f * x);
    float r;
    asm("rcp.approx.f32 %0, %1;" : "=f"(r) : "f"(e + 1.f));
    return fmaf(-2.f, r, 1.f);
}
// pack (a,b) -> fp16x2 word, low half = a
__device__ __forceinline__ uint32_t packh2(float a, float b) {
    __half2 h = __floats2half2_rn(a, b);
    return *reinterpret_cast<uint32_t*>(&h);
}
// pack (a,b) fp32 pair -> hi fp16x2 word + lo (residual) fp16x2 word
__device__ __forceinline__ void split2h(float a, float b, uint32_t& hi, uint32_t& lo) {
    __half ah = __float2half_rn(a), bh = __float2half_rn(b);
    __half al = __float2half_rn(a - __half2float(ah));
    __half bl = __float2half_rn(b - __half2float(bh));
    hi = (uint32_t)__half_as_ushort(ah) | ((uint32_t)__half_as_ushort(bh) << 16);
    lo = (uint32_t)__half_as_ushort(al) | ((uint32_t)__half_as_ushort(bl) << 16);
}
// fast sin/cos with explicit 2-step 2*pi range reduction
__device__ __forceinline__ void fsincos(float x, float& s, float& c) {
    float k = rintf(x * 0.15915494309189535f);
    float r = fmaf(-k, 6.2831855f, x);
    r = fmaf(-k, -1.7484555e-7f, r);
    s = __sinf(r);
    c = __cosf(r);
}
// head weight for output col n, input k
__device__ __forceinline__ float head_w(int k, int n,
    const float* Wvel, const float* Wfh, const float* Wph,
    const float* Wmu, const float* Wstd)
{
    if (n < 2) return Wvel[k * 2 + n];
    if (n < 4) return Wfh[k * 2 + n - 2];
    if (n < 6) return Wph[k * 2 + n - 4];
    if (n == 6) return Wmu[k];
    return Wstd[k];
}

// ---------------- fused prologue kernel ----------------
// blocks [0, 1024): tiled transpose (B,C,H,W) fp32 -> (B,H,W,C/2) half2
// blocks [1024, 1082): trunk weight fragments
// block  1082: head fragments + biases
__global__ void __launch_bounds__(256) prologue_kernel(
    const float* __restrict__ z,
    const float* __restrict__ W1, const float* __restrict__ b1,
    const float* __restrict__ W2, const float* __restrict__ W3,
    const float* __restrict__ Wvel, const float* __restrict__ bvel,
    const float* __restrict__ Wfh,  const float* __restrict__ bfh,
    const float* __restrict__ Wph,  const float* __restrict__ bph,
    const float* __restrict__ Wmu,  const float* __restrict__ bmu,
    const float* __restrict__ Wstd, const float* __restrict__ bstd)
{
    __shared__ uint32_t tile[64][33];     // transpose staging (conflict-free both phases)
    if (blockIdx.x < PRO_TRANS) {
        const int by = blockIdx.x;            // b*64 + y
        const int b = by >> 6, y = by & 63;
        const int tx = threadIdx.x & 63, ty = threadIdx.x >> 6;   // ty: 0..3
        const float* src = z + ((b << 6) << 12) + (y << 6);       // + c*4096 + x
        #pragma unroll
        for (int j = 0; j < 8; j++) {
            int cp = j * 4 + ty;              // channel pair 0..31
            float v0 = __ldg(src + (2 * cp)     * 4096 + tx);
            float v1 = __ldg(src + (2 * cp + 1) * 4096 + tx);
            tile[tx][cp] = packh2(v0, v1);
        }
        __syncthreads();
        const int lane = threadIdx.x & 31, w = threadIdx.x >> 5;  // w: 0..7
        uint32_t* dst = g_zt16 + ((uint32_t)by << 11);            // + x*32 + cpair
        #pragma unroll
        for (int j = 0; j < 8; j++) {
            int x = w * 8 + j;
            dst[(x << 5) + lane] = tile[x][lane];
        }
        return;
    }
    int pbid = blockIdx.x - PRO_TRANS;
    if (pbid < PRO_FRAG) {
        int i = pbid * 256 + threadIdx.x;     // < WF_TOTAL by construction
        int layer, rem;
        const float* W;
        if (i < WF_L2)      { layer = 1; rem = i;          W = W1; }
        else if (i < WF_L3) { layer = 2; rem = i - WF_L2;  W = W2; }
        else                { layer = 3; rem = i - WF_L3;  W = W3; }
        int lane = rem & 31, nt = (rem >> 5) & 15, kt = rem >> 9;
        int n  = nt * 8 + (lane >> 2);
        int k0 = kt * 16 + (lane & 3) * 2;
        float v[4];
        #pragma unroll
        for (int j = 0; j < 4; j++) {
            int k = k0 + (j >> 1) * 8 + (j & 1);
            float val;
            if (layer == 1) {
                if (k < 194)       val = W[k * HID + n];
                else if (k == 194) val = b1[n];
                else               val = 0.f;
            } else {
                val = W[k * HID + n];
            }
            v[j] = val;
        }
        uint2 o;
        o.x = packh2(v[0], v[1]);
        o.y = packh2(v[2], v[3]);
        g_wfrag[i] = o;
    } else {
        int t = threadIdx.x;           // 0..255 = kt*32 + lane
        int lane = t & 31, kt = t >> 5;
        int n  = lane >> 2;
        int k0 = kt * 16 + (lane & 3) * 2;
        float v[4];
        #pragma unroll
        for (int j = 0; j < 4; j++) {
            int k = k0 + (j >> 1) * 8 + (j & 1);
            v[j] = head_w(k, n, Wvel, Wfh, Wph, Wmu, Wstd);
        }
        uint4 o;
        split2h(v[0], v[1], o.x, o.z);
        split2h(v[2], v[3], o.y, o.w);
        g_hfrag[t] = o;
        if (t < 8) {
            float hb;
            if      (t < 2)  hb = bvel[t];
            else if (t < 4)  hb = bfh[t - 2];
            else if (t < 6)  hb = bph[t - 4];
            else if (t == 6) hb = bmu[0];
            else             hb = bstd[0];
            g_hb[t] = hb;
        }
    }
}

// 8-wide batched group: 8 LDG.64 in flight, then 8 independent MMAs
__device__ __forceinline__ void mma_group8_1p(float (*d)[4], const uint32_t* Ah,
                                              const uint2* p, int ntBase) {
    uint2 B[8];
    #pragma unroll
    for (int j = 0; j < 8; j++)
        B[j] = __ldg(p + (ntBase + j) * 32);
    #pragma unroll
    for (int j = 0; j < 8; j++)
        mma_f16(d[ntBase + j], Ah, B[j].x, B[j].y);
}

// ---------------- main kernel ----------------
__global__ void __launch_bounds__(TPB, 4) pinn_main(
    const float* __restrict__ coords, const float* __restrict__ fourierB,
    const float* __restrict__ b2g, const float* __restrict__ b3g,
    float* __restrict__ out)
{
    extern __shared__ __align__(16) unsigned char smem[];
    const uint32_t sb = smem_u32(smem);
    const int tid  = threadIdx.x;
    const int lane = tid & 31;
    const int warp = tid >> 5;        // 0..3, owns rows warp*16..warp*16+15

    float* sb2 = (float*)(smem + SM_B2);
    float* sb3 = (float*)(smem + SM_B3);
    sb2[tid] = b2g[tid];
    sb3[tid] = b3g[tid];

    // ================= warp-coalesced feature build (16 points per warp) ===========
    {
        const int m0w = blockIdx.x * PTS + warp * 16;
        float wa = 0.f, wb = 0.f, wc = 0.f, wd = 0.f, cx = 0.f, cy = 0.f, ct = 0.f;
        int i00 = 0, i01 = 0, i10 = 0, i11 = 0;
        if (lane < 16) {
            int m = m0w + lane;
            cx = coords[m * 3 + 0];
            cy = coords[m * 3 + 1];
            ct = coords[m * 3 + 2];
            int b = m >> 13;
            float fx = (cx + 1.f) * 0.5f * 63.f;
            float fy = (cy + 1.f) * 0.5f * 63.f;
            float x0f = floorf(fx), y0f = floorf(fy);
            int x0 = min(max((int)x0f, 0), 63);
            int x1 = max(min((int)x0f + 1, 63), 0);
            int y0 = min(max((int)y0f, 0), 63);
            int y1 = max(min((int)y0f + 1, 63), 0);
            wa = (x0f + 1.f - fx) * (y0f + 1.f - fy);
            wb = (x0f + 1.f - fx) * (fy - y0f);
            wc = (fx - x0f) * (y0f + 1.f - fy);
            wd = (fx - x0f) * (fy - y0f);
            i00 = (((((b << 6) + y0) << 6) + x0) << 5);   // uint32 row base
            i01 = (((((b << 6) + y1) << 6) + x0) << 5);
            i10 = (((((b << 6) + y0) << 6) + x1) << 5);
            i11 = (((((b << 6) + y1) << 6) + x1) << 5);
        }
        const uint32_t* zt = g_zt16;
        const uint32_t rowBase = SM_A + (uint32_t)(warp * 16) * SA_STRIDE;

        #pragma unroll 4
        for (int i = 0; i < 16; i++) {
            float wwa = __shfl_sync(0xffffffffu, wa, i);
            float wwb = __shfl_sync(0xffffffffu, wb, i);
            float wwc = __shfl_sync(0xffffffffu, wc, i);
            float wwd = __shfl_sync(0xffffffffu, wd, i);
            int a00 = __shfl_sync(0xffffffffu, i00, i);
            int a01 = __shfl_sync(0xffffffffu, i01, i);
            int a10 = __shfl_sync(0xffffffffu, i10, i);
            int a11 = __shfl_sync(0xffffffffu, i11, i);
            uint32_t wA = __ldg(zt + a00 + lane);
            uint32_t wB = __ldg(zt + a01 + lane);
            uint32_t wC = __ldg(zt + a10 + lane);
            uint32_t wD = __ldg(zt + a11 + lane);
            float2 A = __half22float2(*reinterpret_cast<__half2*>(&wA));
            float2 B = __half22float2(*reinterpret_cast<__half2*>(&wB));
            float2 C = __half22float2(*reinterpret_cast<__half2*>(&wC));
            float2 D = __half22float2(*reinterpret_cast<__half2*>(&wD));
            float v0 = wwa * A.x + wwb * B.x + wwc * C.x + wwd * D.x;
            float v1 = wwa * A.y + wwb * B.y + wwc * C.y + wwd * D.y;
            *(uint32_t*)(smem + rowBase + i * SA_STRIDE + lane * 4) = packh2(v0, v1);
        }

        float f0 = __ldg(fourierB + 2 * lane)     * 2.0943951023931953f;
        float f1 = __ldg(fourierB + 2 * lane + 1) * 2.0943951023931953f;
        #pragma unroll 4
        for (int i = 0; i < 16; i++) {
            float t = __shfl_sync(0xffffffffu, ct, i);
            float s0, c0, s1, c1;
            fsincos(f0 * t, s0, c0);
            fsincos(f1 * t, s1, c1);
            *(uint32_t*)(smem + rowBase + i * SA_STRIDE + 128 + lane * 4) = packh2(s0, s1);
            *(uint32_t*)(smem + rowBase + i * SA_STRIDE + 256 + lane * 4) = packh2(c0, c1);
        }

        #pragma unroll 4
        for (int i = 0; i < 16; i++) {
            float xcx = __shfl_sync(0xffffffffu, cx, i);
            float xcy = __shfl_sync(0xffffffffu, cy, i);
            if (lane < 12) {
                uint32_t w = 0;
                if (lane == 0)      w = packh2(xcx, xcy);
                else if (lane == 1) w = packh2(1.f, 0.f);
                *(uint32_t*)(smem + rowBase + i * SA_STRIDE + 384 + lane * 4) = w;
            }
        }
    }
    __syncthreads();   // sb2/sb3 ready

    // ldmatrix A address for this warp's 16 rows
    const uint32_t aAddr = sb + SM_A + (uint32_t)(warp * 16 + (lane & 15)) * SA_STRIDE + (lane >> 4) * 16;

    float d[16][4];

    // ================= layer 1 (A from smem, hi only) =================
    #pragma unroll
    for (int nt = 0; nt < 16; nt++)
        #pragma unroll
        for (int i = 0; i < 4; i++) d[nt][i] = 0.f;
    {
        const uint2* wf = g_wfrag + WF_L1 + lane;
        #pragma unroll 1
        for (int kt = 0; kt < L1_KT; kt++) {
            uint32_t Ah[4];
            ldsm4(Ah, aAddr + kt * 32);
            const uint2* p = wf + kt * 512;
            mma_group8_1p(d, Ah, p, 0);
            mma_group8_1p(d, Ah, p, 8);
        }
    }

    // epilogue 1 -> A2 (fp16, hi only) in registers; D-frag == A-frag layout
    uint32_t A2h[8][4];
    #pragma unroll
    for (int kt = 0; kt < 8; kt++)
        #pragma unroll
        for (int j = 0; j < 4; j++) {
            int srcnt = 2 * kt + (j >> 1);
            int c = (j & 1) * 2;
            A2h[kt][j] = packh2(ftanh(d[srcnt][c]), ftanh(d[srcnt][c + 1]));
        }

    // ================= layer 2 (A in registers) =================
    #pragma unroll
    for (int nt = 0; nt < 16; nt++)
        #pragma unroll
        for (int i = 0; i < 4; i++) d[nt][i] = 0.f;
    {
        const uint2* wf = g_wfrag + WF_L2 + lane;
        #pragma unroll 1
        for (int kt = 0; kt < L23_KT; kt++) {
            const uint2* p = wf + kt * 512;
            mma_group8_1p(d, A2h[kt], p, 0);
            mma_group8_1p(d, A2h[kt], p, 8);
        }
    }

    // epilogue 2: +b2, tanh -> A3 (reuse A2h)
    #pragma unroll
    for (int kt = 0; kt < 8; kt++)
        #pragma unroll
        for (int j = 0; j < 4; j++) {
            int srcnt = 2 * kt + (j >> 1);
            int c = (j & 1) * 2;
            int col = 8 * srcnt + (lane & 3) * 2;
            float2 bb = *(float2*)(sb2 + col);
            A2h[kt][j] = packh2(ftanh(d[srcnt][c] + bb.x), ftanh(d[srcnt][c + 1] + bb.y));
        }

    // ================= layer 3 (A in registers) =================
    #pragma unroll
    for (int nt = 0; nt < 16; nt++)
        #pragma unroll
        for (int i = 0; i < 4; i++) d[nt][i] = 0.f;
    {
        const uint2* wf = g_wfrag + WF_L3 + lane;
        #pragma unroll 1
        for (int kt = 0; kt < L23_KT; kt++) {
            const uint2* p = wf + kt * 512;
            mma_group8_1p(d, A2h[kt], p, 0);
            mma_group8_1p(d, A2h[kt], p, 8);
        }
    }

    // epilogue 3: +b3, tanh -> A4 (reuse A2h)
    #pragma unroll
    for (int kt = 0; kt < 8; kt++)
        #pragma unroll
        for (int j = 0; j < 4; j++) {
            int srcnt = 2 * kt + (j >> 1);
            int c = (j & 1) * 2;
            int col = 8 * srcnt + (lane & 3) * 2;
            float2 bb = *(float2*)(sb3 + col);
            A2h[kt][j] = packh2(ftanh(d[srcnt][c] + bb.x), ftanh(d[srcnt][c + 1] + bb.y));
        }

    // ================= heads as MMA (N=8; W hi+lo, A hi) =================
    {
        float dh[4] = {0.f, 0.f, 0.f, 0.f};
        const uint4* hf = g_hfrag + lane;
        #pragma unroll
        for (int kt = 0; kt < 8; kt++) {
            uint4 HW = __ldg(hf + kt * 32);
            mma_f16(dh, A2h[kt], HW.x, HW.y);   // AhWh
            mma_f16(dh, A2h[kt], HW.z, HW.w);   // AhWl
        }
        int c0 = (lane & 3) * 2;
        int r0 = blockIdx.x * PTS + warp * 16 + (lane >> 2);
        float hb0 = g_hb[c0], hb1 = g_hb[c0 + 1];
        float a0 = dh[0] + hb0, a1 = dh[1] + hb1;
        float a2 = dh[2] + hb0, a3 = dh[3] + hb1;
        if (c0 == 6) {   // col 7 = softplus(.) + MIN_STD
            a1 = fmaxf(a1, 0.f) + log1pf(expf(-fabsf(a1))) + 0.01f;
            a3 = fmaxf(a3, 0.f) + log1pf(expf(-fabsf(a3))) + 0.01f;
        }
        *(float2*)(out + r0 * 8 + c0)       = make_float2(a0, a1);
        *(float2*)(out + (r0 + 8) * 8 + c0) = make_float2(a2, a3);
    }
}

// ---------------- host launch ----------------
extern "C" void kernel_launch(void* const* d_in, const int* in_sizes, int n_in,
                              void* d_out, int out_size) {
    const float* coords   = (const float*)d_in[0];
    const float* z_grid   = (const float*)d_in[1];
    const float* fourierB = (const float*)d_in[2];
    const float* W1   = (const float*)d_in[3];
    const float* b1   = (const float*)d_in[4];
    const float* W2   = (const float*)d_in[5];
    const float* b2   = (const float*)d_in[6];
    const float* W3   = (const float*)d_in[7];
    const float* b3   = (const float*)d_in[8];
    const float* Wvel = (const float*)d_in[9];
    const float* bvel = (const float*)d_in[10];
    const float* Wfh  = (const float*)d_in[11];
    const float* bfh  = (const float*)d_in[12];
    const float* Wph  = (const float*)d_in[13];
    const float* bph  = (const float*)d_in[14];
    const float* Wmu  = (const float*)d_in[15];
    const float* bmu  = (const float*)d_in[16];
    const float* Wstd = (const float*)d_in[17];
    const float* bstd = (const float*)d_in[18];
    float* out = (float*)d_out;

    static bool attr_set = false;
    if (!attr_set) {
        cudaFuncSetAttribute(pinn_main, cudaFuncAttributeMaxDynamicSharedMemorySize, SM_TOTAL);
        attr_set = true;
    }

    prologue_kernel<<<PRO_TOTAL, 256>>>(
        z_grid, W1, b1, W2, W3,
        Wvel, bvel, Wfh, bfh, Wph, bph, Wmu, bmu, Wstd, bstd);
    pinn_main<<<NBLK, TPB, SM_TOTAL>>>(coords, fourierB, b2, b3, out);
}

// round 15
// speedup vs baseline: 2.6846x; 1.0165x over previous
#include <cuda_runtime.h>
#include <cuda_fp16.h>
#include <math.h>
#include <stdint.h>

// ---------------- dims ----------------
#define NPTS 131072
#define PTS  64             // points per block
#define TPB  128            // 4 warps, each owns 16 points x full N=128
#define NBLK (NPTS/PTS)     // 2048
#define HID  128
#define L1_KT 13            // K = 208 (194 real + bias row + pad)
#define L23_KT 8            // K = 128

// ---------------- A smem layout (bytes) ----------------
#define SA_STRIDE 432       // feature row stride: 216 fp16 (16B-aligned)
#define SM_B2 0             // b2: 128 f32
#define SM_B3 512           // b3: 128 f32
#define SM_A  1024
#define SM_TOTAL (SM_A + 64*SA_STRIDE)   // 28672 -> 4 blocks/SM at <=128 regs

// weight fragment array (uint4 units): [layer][kt][ntpair 0..7][lane]
// uint4 = {nt0.b0, nt0.b1, nt1.b0, nt1.b1} fp16x2 words
#define WF_L1 0
#define WF_L2 3328          // 13*256
#define WF_L3 5376          // + 8*256
#define WF_TOTAL4 7424      // + 8*256 = 29 * 256 exactly

// prologue grid split
#define PRO_TRANS 1024      // transpose blocks (b*64+y)
#define PRO_FRAG  29        // trunk fragment blocks (uint4 units)
#define PRO_TOTAL (PRO_TRANS + PRO_FRAG + 1)

// ---------------- device scratch ----------------
__device__ uint32_t g_zt16[16*64*64*32];     // z transposed (B,H,W,C/2) packed half2
__device__ uint4 g_wfrag4[WF_TOTAL4];        // paired MMA b-fragments
__device__ uint4 g_hfrag[8*32];              // head b-fragments {b0h,b1h,b0l,b1l}
__device__ float g_hb[8];                    // head biases

// ---------------- helpers ----------------
__device__ __forceinline__ uint32_t smem_u32(const void* p) {
    uint32_t a;
    asm("{ .reg .u64 t; cvta.to.shared.u64 t, %1; cvt.u32.u64 %0, t; }" : "=r"(a) : "l"(p));
    return a;
}
__device__ __forceinline__ void ldsm4(uint32_t* r, uint32_t a) {
    asm volatile("ldmatrix.sync.aligned.m8n8.x4.shared.b16 {%0,%1,%2,%3}, [%4];"
                 : "=r"(r[0]), "=r"(r[1]), "=r"(r[2]), "=r"(r[3]) : "r"(a));
}
__device__ __forceinline__ void mma_f16(float* d, const uint32_t* a, uint32_t b0, uint32_t b1) {
    asm volatile("mma.sync.aligned.m16n8k16.row.col.f32.f16.f16.f32 "
                 "{%0,%1,%2,%3}, {%4,%5,%6,%7}, {%8,%9}, {%0,%1,%2,%3};"
                 : "+f"(d[0]), "+f"(d[1]), "+f"(d[2]), "+f"(d[3])
                 : "r"(a[0]), "r"(a[1]), "r"(a[2]), "r"(a[3]), "r"(b0), "r"(b1));
}
// zero-init form: d = a*b + 0 (skips explicit accumulator clearing)
__device__ __forceinline__ void mma_f16_z(float* d, const uint32_t* a, uint32_t b0, uint32_t b1) {
    asm volatile("mma.sync.aligned.m16n8k16.row.col.f32.f16.f16.f32 "
                 "{%0,%1,%2,%3}, {%4,%5,%6,%7}, {%8,%9}, {%10,%10,%10,%10};"
                 : "=f"(d[0]), "=f"(d[1]), "=f"(d[2]), "=f"(d[3])
                 : "r"(a[0]), "r"(a[1]), "r"(a[2]), "r"(a[3]), "r"(b0), "r"(b1), "f"(0.f));
}
// fast tanh: 1 - 2/(exp(2x)+1); ~1e-6 abs err
__device__ __forceinline__ float ftanh(float x) {
    float e = __expf(2.f * x);
    float r;
    asm("rcp.approx.f32 %0, %1;" : "=f"(r) : "f"(e + 1.f));
    return fmaf(-2.f, r, 1.f);
}
// pack (a,b) -> fp16x2 word, low half = a
__device__ __forceinline__ uint32_t packh2(float a, float b) {
    __half2 h = __floats2half2_rn(a, b);
    return *reinterpret_cast<uint32_t*>(&h);
}
// pack (a,b) fp32 pair -> hi fp16x2 word + lo (residual) fp16x2 word
__device__ __forceinline__ void split2h(float a, float b, uint32_t& hi, uint32_t& lo) {
    __half ah = __float2half_rn(a), bh = __float2half_rn(b);
    __half al = __float2half_rn(a - __half2float(ah));
    __half bl = __float2half_rn(b - __half2float(bh));
    hi = (uint32_t)__half_as_ushort(ah) | ((uint32_t)__half_as_ushort(bh) << 16);
    lo = (uint32_t)__half_as_ushort(al) | ((uint32_t)__half_as_ushort(bl) << 16);
}
// fast sin/cos with explicit 2-step 2*pi range reduction
__device__ __forceinline__ void fsincos(float x, float& s, float& c) {
    float k = rintf(x * 0.15915494309189535f);
    float r = fmaf(-k, 6.2831855f, x);
    r = fmaf(-k, -1.7484555e-7f, r);
    s = __sinf(r);
    c = __cosf(r);
}
// head weight for output col n, input k
__device__ __forceinline__ float head_w(int k, int n,
    const float* Wvel, const float* Wfh, const float* Wph,
    const float* Wmu, const float* Wstd)
{
    if (n < 2) return Wvel[k * 2 + n];
    if (n < 4) return Wfh[k * 2 + n - 2];
    if (n < 6) return Wph[k * 2 + n - 4];
    if (n == 6) return Wmu[k];
    return Wstd[k];
}
// trunk weight for (layer, k, n)
__device__ __forceinline__ float trunk_w(int layer, int k, int n,
    const float* W1, const float* b1, const float* W2, const float* W3)
{
    if (layer == 1) {
        if (k < 194)  return W1[k * HID + n];
        if (k == 194) return b1[n];
        return 0.f;
    }
    const float* W = (layer == 2) ? W2 : W3;
    return W[k * HID + n];
}

// ---------------- fused prologue kernel ----------------
// blocks [0, 1024): tiled transpose (B,C,H,W) fp32 -> (B,H,W,C/2) half2
// blocks [1024, 1053): trunk weight fragments (uint4 pairs)
// block  1053: head fragments + biases
__global__ void __launch_bounds__(256) prologue_kernel(
    const float* __restrict__ z,
    const float* __restrict__ W1, const float* __restrict__ b1,
    const float* __restrict__ W2, const float* __restrict__ W3,
    const float* __restrict__ Wvel, const float* __restrict__ bvel,
    const float* __restrict__ Wfh,  const float* __restrict__ bfh,
    const float* __restrict__ Wph,  const float* __restrict__ bph,
    const float* __restrict__ Wmu,  const float* __restrict__ bmu,
    const float* __restrict__ Wstd, const float* __restrict__ bstd)
{
    __shared__ uint32_t tile[64][33];     // transpose staging (conflict-free both phases)
    if (blockIdx.x < PRO_TRANS) {
        const int by = blockIdx.x;            // b*64 + y
        const int b = by >> 6, y = by & 63;
        const int tx = threadIdx.x & 63, ty = threadIdx.x >> 6;   // ty: 0..3
        const float* src = z + ((b << 6) << 12) + (y << 6);       // + c*4096 + x
        #pragma unroll
        for (int j = 0; j < 8; j++) {
            int cp = j * 4 + ty;              // channel pair 0..31
            float v0 = __ldg(src + (2 * cp)     * 4096 + tx);
            float v1 = __ldg(src + (2 * cp + 1) * 4096 + tx);
            tile[tx][cp] = packh2(v0, v1);
        }
        __syncthreads();
        const int lane = threadIdx.x & 31, w = threadIdx.x >> 5;  // w: 0..7
        uint32_t* dst = g_zt16 + ((uint32_t)by << 11);            // + x*32 + cpair
        #pragma unroll
        for (int j = 0; j < 8; j++) {
            int x = w * 8 + j;
            dst[(x << 5) + lane] = tile[x][lane];
        }
        return;
    }
    int pbid = blockIdx.x - PRO_TRANS;
    if (pbid < PRO_FRAG) {
        int i = pbid * 256 + threadIdx.x;     // < WF_TOTAL4 by construction
        int layer, rem;
        if (i < WF_L2)      { layer = 1; rem = i; }
        else if (i < WF_L3) { layer = 2; rem = i - WF_L2; }
        else                { layer = 3; rem = i - WF_L3; }
        int lane = rem & 31, np = (rem >> 5) & 7, kt = rem >> 8;
        int k0 = kt * 16 + (lane & 3) * 2;
        uint32_t w[4];
        #pragma unroll
        for (int h = 0; h < 2; h++) {
            int n = (2 * np + h) * 8 + (lane >> 2);
            float v[4];
            #pragma unroll
            for (int j = 0; j < 4; j++) {
                int k = k0 + (j >> 1) * 8 + (j & 1);
                v[j] = trunk_w(layer, k, n, W1, b1, W2, W3);
            }
            w[2 * h]     = packh2(v[0], v[1]);
            w[2 * h + 1] = packh2(v[2], v[3]);
        }
        g_wfrag4[i] = make_uint4(w[0], w[1], w[2], w[3]);
    } else {
        int t = threadIdx.x;           // 0..255 = kt*32 + lane
        int lane = t & 31, kt = t >> 5;
        int n  = lane >> 2;
        int k0 = kt * 16 + (lane & 3) * 2;
        float v[4];
        #pragma unroll
        for (int j = 0; j < 4; j++) {
            int k = k0 + (j >> 1) * 8 + (j & 1);
            v[j] = head_w(k, n, Wvel, Wfh, Wph, Wmu, Wstd);
        }
        uint4 o;
        split2h(v[0], v[1], o.x, o.z);
        split2h(v[2], v[3], o.y, o.w);
        g_hfrag[t] = o;
        if (t < 8) {
            float hb;
            if      (t < 2)  hb = bvel[t];
            else if (t < 4)  hb = bfh[t - 2];
            else if (t < 6)  hb = bph[t - 4];
            else if (t == 6) hb = bmu[0];
            else             hb = bstd[0];
            g_hb[t] = hb;
        }
    }
}

// 8 n-tiles via 4 LDG.128 (paired fragments), accumulate form
__device__ __forceinline__ void mma_group8_u4(float (*d)[4], const uint32_t* Ah,
                                              const uint4* p, int npBase) {
    uint4 B[4];
    #pragma unroll
    for (int j = 0; j < 4; j++)
        B[j] = __ldg(p + (npBase + j) * 32);
    #pragma unroll
    for (int j = 0; j < 4; j++) {
        mma_f16(d[2 * (npBase + j)],     Ah, B[j].x, B[j].y);
        mma_f16(d[2 * (npBase + j) + 1], Ah, B[j].z, B[j].w);
    }
}
// zero-init form (first k-tile of a layer)
__device__ __forceinline__ void mma_group8_u4_z(float (*d)[4], const uint32_t* Ah,
                                                const uint4* p, int npBase) {
    uint4 B[4];
    #pragma unroll
    for (int j = 0; j < 4; j++)
        B[j] = __ldg(p + (npBase + j) * 32);
    #pragma unroll
    for (int j = 0; j < 4; j++) {
        mma_f16_z(d[2 * (npBase + j)],     Ah, B[j].x, B[j].y);
        mma_f16_z(d[2 * (npBase + j) + 1], Ah, B[j].z, B[j].w);
    }
}

// ---------------- main kernel ----------------
__global__ void __launch_bounds__(TPB, 4) pinn_main(
    const float* __restrict__ coords, const float* __restrict__ fourierB,
    const float* __restrict__ b2g, const float* __restrict__ b3g,
    float* __restrict__ out)
{
    extern __shared__ __align__(16) unsigned char smem[];
    const uint32_t sb = smem_u32(smem);
    const int tid  = threadIdx.x;
    const int lane = tid & 31;
    const int warp = tid >> 5;        // 0..3, owns rows warp*16..warp*16+15

    float* sb2 = (float*)(smem + SM_B2);
    float* sb3 = (float*)(smem + SM_B3);
    sb2[tid] = b2g[tid];
    sb3[tid] = b3g[tid];

    // ================= warp-coalesced feature build (16 points per warp) ===========
    {
        const int m0w = blockIdx.x * PTS + warp * 16;
        float wa = 0.f, wb = 0.f, wc = 0.f, wd = 0.f, cx = 0.f, cy = 0.f, ct = 0.f;
        int i00 = 0, i01 = 0, i10 = 0, i11 = 0;
        if (lane < 16) {
            int m = m0w + lane;
            cx = coords[m * 3 + 0];
            cy = coords[m * 3 + 1];
            ct = coords[m * 3 + 2];
            int b = m >> 13;
            float fx = (cx + 1.f) * 0.5f * 63.f;
            float fy = (cy + 1.f) * 0.5f * 63.f;
            float x0f = floorf(fx), y0f = floorf(fy);
            int x0 = min(max((int)x0f, 0), 63);
            int x1 = max(min((int)x0f + 1, 63), 0);
            int y0 = min(max((int)y0f, 0), 63);
            int y1 = max(min((int)y0f + 1, 63), 0);
            wa = (x0f + 1.f - fx) * (y0f + 1.f - fy);
            wb = (x0f + 1.f - fx) * (fy - y0f);
            wc = (fx - x0f) * (y0f + 1.f - fy);
            wd = (fx - x0f) * (fy - y0f);
            i00 = (((((b << 6) + y0) << 6) + x0) << 5);   // uint32 row base
            i01 = (((((b << 6) + y1) << 6) + x0) << 5);
            i10 = (((((b << 6) + y0) << 6) + x1) << 5);
            i11 = (((((b << 6) + y1) << 6) + x1) << 5);
        }
        const uint32_t* zt = g_zt16;
        const uint32_t rowBase = SM_A + (uint32_t)(warp * 16) * SA_STRIDE;

        #pragma unroll 4
        for (int i = 0; i < 16; i++) {
            float wwa = __shfl_sync(0xffffffffu, wa, i);
            float wwb = __shfl_sync(0xffffffffu, wb, i);
            float wwc = __shfl_sync(0xffffffffu, wc, i);
            float wwd = __shfl_sync(0xffffffffu, wd, i);
            int a00 = __shfl_sync(0xffffffffu, i00, i);
            int a01 = __shfl_sync(0xffffffffu, i01, i);
            int a10 = __shfl_sync(0xffffffffu, i10, i);
            int a11 = __shfl_sync(0xffffffffu, i11, i);
            uint32_t wA = __ldg(zt + a00 + lane);
            uint32_t wB = __ldg(zt + a01 + lane);
            uint32_t wC = __ldg(zt + a10 + lane);
            uint32_t wD = __ldg(zt + a11 + lane);
            float2 A = __half22float2(*reinterpret_cast<__half2*>(&wA));
            float2 B = __half22float2(*reinterpret_cast<__half2*>(&wB));
            float2 C = __half22float2(*reinterpret_cast<__half2*>(&wC));
            float2 D = __half22float2(*reinterpret_cast<__half2*>(&wD));
            float v0 = wwa * A.x + wwb * B.x + wwc * C.x + wwd * D.x;
            float v1 = wwa * A.y + wwb * B.y + wwc * C.y + wwd * D.y;
            *(uint32_t*)(smem + rowBase + i * SA_STRIDE + lane * 4) = packh2(v0, v1);
        }

        float f0 = __ldg(fourierB + 2 * lane)     * 2.0943951023931953f;
        float f1 = __ldg(fourierB + 2 * lane + 1) * 2.0943951023931953f;
        #pragma unroll 4
        for (int i = 0; i < 16; i++) {
            float t = __shfl_sync(0xffffffffu, ct, i);
            float s0, c0, s1, c1;
            fsincos(f0 * t, s0, c0);
            fsincos(f1 * t, s1, c1);
            *(uint32_t*)(smem + rowBase + i * SA_STRIDE + 128 + lane * 4) = packh2(s0, s1);
            *(uint32_t*)(smem + rowBase + i * SA_STRIDE + 256 + lane * 4) = packh2(c0, c1);
        }

        #pragma unroll 4
        for (int i = 0; i < 16; i++) {
            float xcx = __shfl_sync(0xffffffffu, cx, i);
            float xcy = __shfl_sync(0xffffffffu, cy, i);
            if (lane < 12) {
                uint32_t w = 0;
                if (lane == 0)      w = packh2(xcx, xcy);
                else if (lane == 1) w = packh2(1.f, 0.f);
                *(uint32_t*)(smem + rowBase + i * SA_STRIDE + 384 + lane * 4) = w;
            }
        }
    }
    __syncthreads();   // sb2/sb3 ready

    // ldmatrix A address for this warp's 16 rows
    const uint32_t aAddr = sb + SM_A + (uint32_t)(warp * 16 + (lane & 15)) * SA_STRIDE + (lane >> 4) * 16;

    float d[16][4];

    // ================= layer 1 (A from smem, hi only) =================
    {
        const uint4* wf = g_wfrag4 + WF_L1 + lane;
        uint32_t Ah[4];
        ldsm4(Ah, aAddr);
        mma_group8_u4_z(d, Ah, wf, 0);
        mma_group8_u4_z(d, Ah, wf, 4);
        #pragma unroll 1
        for (int kt = 1; kt < L1_KT; kt++) {
            ldsm4(Ah, aAddr + kt * 32);
            const uint4* p = wf + kt * 256;
            mma_group8_u4(d, Ah, p, 0);
            mma_group8_u4(d, Ah, p, 4);
        }
    }

    // epilogue 1 -> A2 (fp16, hi only) in registers; D-frag == A-frag layout
    uint32_t A2h[8][4];
    #pragma unroll
    for (int kt = 0; kt < 8; kt++)
        #pragma unroll
        for (int j = 0; j < 4; j++) {
            int srcnt = 2 * kt + (j >> 1);
            int c = (j & 1) * 2;
            A2h[kt][j] = packh2(ftanh(d[srcnt][c]), ftanh(d[srcnt][c + 1]));
        }

    // ================= layer 2 (A in registers) =================
    {
        const uint4* wf = g_wfrag4 + WF_L2 + lane;
        mma_group8_u4_z(d, A2h[0], wf, 0);
        mma_group8_u4_z(d, A2h[0], wf, 4);
        #pragma unroll 1
        for (int kt = 1; kt < L23_KT; kt++) {
            const uint4* p = wf + kt * 256;
            mma_group8_u4(d, A2h[kt], p, 0);
            mma_group8_u4(d, A2h[kt], p, 4);
        }
    }

    // epilogue 2: +b2, tanh -> A3 (reuse A2h)
    #pragma unroll
    for (int kt = 0; kt < 8; kt++)
        #pragma unroll
        for (int j = 0; j < 4; j++) {
            int srcnt = 2 * kt + (j >> 1);
            int c = (j & 1) * 2;
            int col = 8 * srcnt + (lane & 3) * 2;
            float2 bb = *(float2*)(sb2 + col);
            A2h[kt][j] = packh2(ftanh(d[srcnt][c] + bb.x), ftanh(d[srcnt][c + 1] + bb.y));
        }

    // ================= layer 3 (A in registers) =================
    {
        const uint4* wf = g_wfrag4 + WF_L3 + lane;
        mma_group8_u4_z(d, A2h[0], wf, 0);
        mma_group8_u4_z(d, A2h[0], wf, 4);
        #pragma unroll 1
        for (int kt = 1; kt < L23_KT; kt++) {
            const uint4* p = wf + kt * 256;
            mma_group8_u4(d, A2h[kt], p, 0);
            mma_group8_u4(d, A2h[kt], p, 4);
        }
    }

    // epilogue 3: +b3, tanh -> A4 (reuse A2h)
    #pragma unroll
    for (int kt = 0; kt < 8; kt++)
        #pragma unroll
        for (int j = 0; j < 4; j++) {
            int srcnt = 2 * kt + (j >> 1);
            int c = (j & 1) * 2;
            int col = 8 * srcnt + (lane & 3) * 2;
            float2 bb = *(float2*)(sb3 + col);
            A2h[kt][j] = packh2(ftanh(d[srcnt][c] + bb.x), ftanh(d[srcnt][c + 1] + bb.y));
        }

    // ================= heads as MMA (N=8; W hi+lo, A hi) =================
    {
        float dh[4];
        const uint4* hf = g_hfrag + lane;
        {
            uint4 HW = __ldg(hf);
            mma_f16_z(dh, A2h[0], HW.x, HW.y);
            mma_f16(dh, A2h[0], HW.z, HW.w);
        }
        #pragma unroll
        for (int kt = 1; kt < 8; kt++) {
            uint4 HW = __ldg(hf + kt * 32);
            mma_f16(dh, A2h[kt], HW.x, HW.y);   // AhWh
            mma_f16(dh, A2h[kt], HW.z, HW.w);   // AhWl
        }
        int c0 = (lane & 3) * 2;
        int r0 = blockIdx.x * PTS + warp * 16 + (lane >> 2);
        float hb0 = g_hb[c0], hb1 = g_hb[c0 + 1];
        float a0 = dh[0] + hb0, a1 = dh[1] + hb1;
        float a2 = dh[2] + hb0, a3 = dh[3] + hb1;
        if (c0 == 6) {   // col 7 = softplus(.) + MIN_STD
            a1 = fmaxf(a1, 0.f) + log1pf(expf(-fabsf(a1))) + 0.01f;
            a3 = fmaxf(a3, 0.f) + log1pf(expf(-fabsf(a3))) + 0.01f;
        }
        *(float2*)(out + r0 * 8 + c0)       = make_float2(a0, a1);
        *(float2*)(out + (r0 + 8) * 8 + c0) = make_float2(a2, a3);
    }
}

// ---------------- host launch ----------------
extern "C" void kernel_launch(void* const* d_in, const int* in_sizes, int n_in,
                              void* d_out, int out_size) {
    const float* coords   = (const float*)d_in[0];
    const float* z_grid   = (const float*)d_in[1];
    const float* fourierB = (const float*)d_in[2];
    const float* W1   = (const float*)d_in[3];
    const float* b1   = (const float*)d_in[4];
    const float* W2   = (const float*)d_in[5];
    const float* b2   = (const float*)d_in[6];
    const float* W3   = (const float*)d_in[7];
    const float* b3   = (const float*)d_in[8];
    const float* Wvel = (const float*)d_in[9];
    const float* bvel = (const float*)d_in[10];
    const float* Wfh  = (const float*)d_in[11];
    const float* bfh  = (const float*)d_in[12];
    const float* Wph  = (const float*)d_in[13];
    const float* bph  = (const float*)d_in[14];
    const float* Wmu  = (const float*)d_in[15];
    const float* bmu  = (const float*)d_in[16];
    const float* Wstd = (const float*)d_in[17];
    const float* bstd = (const float*)d_in[18];
    float* out = (float*)d_out;

    static bool attr_set = false;
    if (!attr_set) {
        cudaFuncSetAttribute(pinn_main, cudaFuncAttributeMaxDynamicSharedMemorySize, SM_TOTAL);
        attr_set = true;
    }

    prologue_kernel<<<PRO_TOTAL, 256>>>(
        z_grid, W1, b1, W2, W3,
        Wvel, bvel, Wfh, bfh, Wph, bph, Wmu, bmu, Wstd, bstd);
    pinn_main<<<NBLK, TPB, SM_TOTAL>>>(coords, fourierB, b2, b3, out);
}

// round 16
// speedup vs baseline: 3.0025x; 1.1184x over previous
#include <cuda_runtime.h>
#include <cuda_fp16.h>
#include <math.h>
#include <stdint.h>

// ---------------- dims ----------------
#define NPTS 131072
#define PTS  64             // points per block
#define TPB  128            // 4 warps, each owns 16 points x full N=128
#define NBLK (NPTS/PTS)     // 2048
#define HID  128
#define L1_KT 13            // K = 208 (194 real + bias row + pad)
#define L23_KT 8            // K = 128

// ---------------- A smem layout (bytes) ----------------
#define SA_STRIDE 432       // feature row stride: 216 fp16 (16B-aligned)
#define SM_B2 0             // b2: 128 f32
#define SM_B3 512           // b3: 128 f32
#define SM_A  1024
#define SM_TOTAL (SM_A + 64*SA_STRIDE)   // 28672 -> 4 blocks/SM at <=128 regs

// weight fragment array (uint4 units): [layer][kt][ntpair 0..7][lane]
#define WF_L1 0
#define WF_L2 3328          // 13*256
#define WF_L3 5376          // + 8*256
#define WF_TOTAL4 7424      // + 8*256 = 29 * 256 exactly

// prologue grid split
#define PRO_TRANS 1024
#define PRO_FRAG  29
#define PRO_TOTAL (PRO_TRANS + PRO_FRAG + 1)

// ---------------- device scratch ----------------
__device__ uint32_t g_zt16[16*64*64*32];     // z transposed (B,H,W,C/2) packed half2
__device__ uint4 g_wfrag4[WF_TOTAL4];        // paired MMA b-fragments
__device__ uint4 g_hfrag[8*32];              // head b-fragments {b0h,b1h,b0l,b1l}
__device__ float g_hb[8];                    // head biases

// ---------------- helpers ----------------
__device__ __forceinline__ uint32_t smem_u32(const void* p) {
    uint32_t a;
    asm("{ .reg .u64 t; cvta.to.shared.u64 t, %1; cvt.u32.u64 %0, t; }" : "=r"(a) : "l"(p));
    return a;
}
__device__ __forceinline__ void ldsm4(uint32_t* r, uint32_t a) {
    asm volatile("ldmatrix.sync.aligned.m8n8.x4.shared.b16 {%0,%1,%2,%3}, [%4];"
                 : "=r"(r[0]), "=r"(r[1]), "=r"(r[2]), "=r"(r[3]) : "r"(a));
}
__device__ __forceinline__ void mma_f16(float* d, const uint32_t* a, uint32_t b0, uint32_t b1) {
    asm volatile("mma.sync.aligned.m16n8k16.row.col.f32.f16.f16.f32 "
                 "{%0,%1,%2,%3}, {%4,%5,%6,%7}, {%8,%9}, {%0,%1,%2,%3};"
                 : "+f"(d[0]), "+f"(d[1]), "+f"(d[2]), "+f"(d[3])
                 : "r"(a[0]), "r"(a[1]), "r"(a[2]), "r"(a[3]), "r"(b0), "r"(b1));
}
__device__ __forceinline__ void mma_f16_z(float* d, const uint32_t* a, uint32_t b0, uint32_t b1) {
    asm volatile("mma.sync.aligned.m16n8k16.row.col.f32.f16.f16.f32 "
                 "{%0,%1,%2,%3}, {%4,%5,%6,%7}, {%8,%9}, {%10,%10,%10,%10};"
                 : "=f"(d[0]), "=f"(d[1]), "=f"(d[2]), "=f"(d[3])
                 : "r"(a[0]), "r"(a[1]), "r"(a[2]), "r"(a[3]), "r"(b0), "r"(b1), "f"(0.f));
}
// fast tanh (prologue-side fp32 use only)
__device__ __forceinline__ float ftanh(float x) {
    float e = __expf(2.f * x);
    float r;
    asm("rcp.approx.f32 %0, %1;" : "=f"(r) : "f"(e + 1.f));
    return fmaf(-2.f, r, 1.f);
}
// hardware packed tanh: one MUFU op, two fp16 lanes
__device__ __forceinline__ uint32_t tanh_h2(uint32_t x) {
    uint32_t r;
    asm("tanh.approx.f16x2 %0, %1;" : "=r"(r) : "r"(x));
    return r;
}
// pack (a,b) -> fp16x2 word, low half = a
__device__ __forceinline__ uint32_t packh2(float a, float b) {
    __half2 h = __floats2half2_rn(a, b);
    return *reinterpret_cast<uint32_t*>(&h);
}
// pack (a,b) fp32 pair -> hi fp16x2 word + lo (residual) fp16x2 word
__device__ __forceinline__ void split2h(float a, float b, uint32_t& hi, uint32_t& lo) {
    __half ah = __float2half_rn(a), bh = __float2half_rn(b);
    __half al = __float2half_rn(a - __half2float(ah));
    __half bl = __float2half_rn(b - __half2float(bh));
    hi = (uint32_t)__half_as_ushort(ah) | ((uint32_t)__half_as_ushort(bh) << 16);
    lo = (uint32_t)__half_as_ushort(al) | ((uint32_t)__half_as_ushort(bl) << 16);
}
// fast sin/cos with explicit 2-step 2*pi range reduction
__device__ __forceinline__ void fsincos(float x, float& s, float& c) {
    float k = rintf(x * 0.15915494309189535f);
    float r = fmaf(-k, 6.2831855f, x);
    r = fmaf(-k, -1.7484555e-7f, r);
    s = __sinf(r);
    c = __cosf(r);
}
// head weight for output col n, input k
__device__ __forceinline__ float head_w(int k, int n,
    const float* Wvel, const float* Wfh, const float* Wph,
    const float* Wmu, const float* Wstd)
{
    if (n < 2) return Wvel[k * 2 + n];
    if (n < 4) return Wfh[k * 2 + n - 2];
    if (n < 6) return Wph[k * 2 + n - 4];
    if (n == 6) return Wmu[k];
    return Wstd[k];
}
// trunk weight for (layer, k, n)
__device__ __forceinline__ float trunk_w(int layer, int k, int n,
    const float* W1, const float* b1, const float* W2, const float* W3)
{
    if (layer == 1) {
        if (k < 194)  return W1[k * HID + n];
        if (k == 194) return b1[n];
        return 0.f;
    }
    const float* W = (layer == 2) ? W2 : W3;
    return W[k * HID + n];
}

// ---------------- fused prologue kernel ----------------
__global__ void __launch_bounds__(256) prologue_kernel(
    const float* __restrict__ z,
    const float* __restrict__ W1, const float* __restrict__ b1,
    const float* __restrict__ W2, const float* __restrict__ W3,
    const float* __restrict__ Wvel, const float* __restrict__ bvel,
    const float* __restrict__ Wfh,  const float* __restrict__ bfh,
    const float* __restrict__ Wph,  const float* __restrict__ bph,
    const float* __restrict__ Wmu,  const float* __restrict__ bmu,
    const float* __restrict__ Wstd, const float* __restrict__ bstd)
{
    __shared__ uint32_t tile[64][33];
    if (blockIdx.x < PRO_TRANS) {
        const int by = blockIdx.x;            // b*64 + y
        const int b = by >> 6, y = by & 63;
        const int tx = threadIdx.x & 63, ty = threadIdx.x >> 6;
        const float* src = z + ((b << 6) << 12) + (y << 6);
        #pragma unroll
        for (int j = 0; j < 8; j++) {
            int cp = j * 4 + ty;
            float v0 = __ldg(src + (2 * cp)     * 4096 + tx);
            float v1 = __ldg(src + (2 * cp + 1) * 4096 + tx);
            tile[tx][cp] = packh2(v0, v1);
        }
        __syncthreads();
        const int lane = threadIdx.x & 31, w = threadIdx.x >> 5;
        uint32_t* dst = g_zt16 + ((uint32_t)by << 11);
        #pragma unroll
        for (int j = 0; j < 8; j++) {
            int x = w * 8 + j;
            dst[(x << 5) + lane] = tile[x][lane];
        }
        return;
    }
    int pbid = blockIdx.x - PRO_TRANS;
    if (pbid < PRO_FRAG) {
        int i = pbid * 256 + threadIdx.x;
        int layer, rem;
        if (i < WF_L2)      { layer = 1; rem = i; }
        else if (i < WF_L3) { layer = 2; rem = i - WF_L2; }
        else                { layer = 3; rem = i - WF_L3; }
        int lane = rem & 31, np = (rem >> 5) & 7, kt = rem >> 8;
        int k0 = kt * 16 + (lane & 3) * 2;
        uint32_t w[4];
        #pragma unroll
        for (int h = 0; h < 2; h++) {
            int n = (2 * np + h) * 8 + (lane >> 2);
            float v[4];
            #pragma unroll
            for (int j = 0; j < 4; j++) {
                int k = k0 + (j >> 1) * 8 + (j & 1);
                v[j] = trunk_w(layer, k, n, W1, b1, W2, W3);
            }
            w[2 * h]     = packh2(v[0], v[1]);
            w[2 * h + 1] = packh2(v[2], v[3]);
        }
        g_wfrag4[i] = make_uint4(w[0], w[1], w[2], w[3]);
    } else {
        int t = threadIdx.x;
        int lane = t & 31, kt = t >> 5;
        int n  = lane >> 2;
        int k0 = kt * 16 + (lane & 3) * 2;
        float v[4];
        #pragma unroll
        for (int j = 0; j < 4; j++) {
            int k = k0 + (j >> 1) * 8 + (j & 1);
            v[j] = head_w(k, n, Wvel, Wfh, Wph, Wmu, Wstd);
        }
        uint4 o;
        split2h(v[0], v[1], o.x, o.z);
        split2h(v[2], v[3], o.y, o.w);
        g_hfrag[t] = o;
        if (t < 8) {
            float hb;
            if      (t < 2)  hb = bvel[t];
            else if (t < 4)  hb = bfh[t - 2];
            else if (t < 6)  hb = bph[t - 4];
            else if (t == 6) hb = bmu[0];
            else             hb = bstd[0];
            g_hb[t] = hb;
        }
    }
}

// 8 n-tiles via 4 LDG.128 (paired fragments), accumulate form
__device__ __forceinline__ void mma_group8_u4(float (*d)[4], const uint32_t* Ah,
                                              const uint4* p, int npBase) {
    uint4 B[4];
    #pragma unroll
    for (int j = 0; j < 4; j++)
        B[j] = __ldg(p + (npBase + j) * 32);
    #pragma unroll
    for (int j = 0; j < 4; j++) {
        mma_f16(d[2 * (npBase + j)],     Ah, B[j].x, B[j].y);
        mma_f16(d[2 * (npBase + j) + 1], Ah, B[j].z, B[j].w);
    }
}
__device__ __forceinline__ void mma_group8_u4_z(float (*d)[4], const uint32_t* Ah,
                                                const uint4* p, int npBase) {
    uint4 B[4];
    #pragma unroll
    for (int j = 0; j < 4; j++)
        B[j] = __ldg(p + (npBase + j) * 32);
    #pragma unroll
    for (int j = 0; j < 4; j++) {
        mma_f16_z(d[2 * (npBase + j)],     Ah, B[j].x, B[j].y);
        mma_f16_z(d[2 * (npBase + j) + 1], Ah, B[j].z, B[j].w);
    }
}

// ---------------- main kernel ----------------
__global__ void __launch_bounds__(TPB, 4) pinn_main(
    const float* __restrict__ coords, const float* __restrict__ fourierB,
    const float* __restrict__ b2g, const float* __restrict__ b3g,
    float* __restrict__ out)
{
    extern __shared__ __align__(16) unsigned char smem[];
    const uint32_t sb = smem_u32(smem);
    const int tid  = threadIdx.x;
    const int lane = tid & 31;
    const int warp = tid >> 5;        // 0..3, owns rows warp*16..warp*16+15

    float* sb2 = (float*)(smem + SM_B2);
    float* sb3 = (float*)(smem + SM_B3);
    sb2[tid] = b2g[tid];
    sb3[tid] = b3g[tid];

    // ================= warp-coalesced feature build (16 points per warp) ===========
    {
        const int m0w = blockIdx.x * PTS + warp * 16;
        float wa = 0.f, wb = 0.f, wc = 0.f, wd = 0.f, cx = 0.f, cy = 0.f, ct = 0.f;
        int i00 = 0, i01 = 0, i10 = 0, i11 = 0;
        if (lane < 16) {
            int m = m0w + lane;
            cx = coords[m * 3 + 0];
            cy = coords[m * 3 + 1];
            ct = coords[m * 3 + 2];
            int b = m >> 13;
            float fx = (cx + 1.f) * 0.5f * 63.f;
            float fy = (cy + 1.f) * 0.5f * 63.f;
            float x0f = floorf(fx), y0f = floorf(fy);
            int x0 = min(max((int)x0f, 0), 63);
            int x1 = max(min((int)x0f + 1, 63), 0);
            int y0 = min(max((int)y0f, 0), 63);
            int y1 = max(min((int)y0f + 1, 63), 0);
            wa = (x0f + 1.f - fx) * (y0f + 1.f - fy);
            wb = (x0f + 1.f - fx) * (fy - y0f);
            wc = (fx - x0f) * (y0f + 1.f - fy);
            wd = (fx - x0f) * (fy - y0f);
            i00 = (((((b << 6) + y0) << 6) + x0) << 5);
            i01 = (((((b << 6) + y1) << 6) + x0) << 5);
            i10 = (((((b << 6) + y0) << 6) + x1) << 5);
            i11 = (((((b << 6) + y1) << 6) + x1) << 5);
        }
        const uint32_t* zt = g_zt16;
        const uint32_t rowBase = SM_A + (uint32_t)(warp * 16) * SA_STRIDE;

        #pragma unroll 4
        for (int i = 0; i < 16; i++) {
            float wwa = __shfl_sync(0xffffffffu, wa, i);
            float wwb = __shfl_sync(0xffffffffu, wb, i);
            float wwc = __shfl_sync(0xffffffffu, wc, i);
            float wwd = __shfl_sync(0xffffffffu, wd, i);
            int a00 = __shfl_sync(0xffffffffu, i00, i);
            int a01 = __shfl_sync(0xffffffffu, i01, i);
            int a10 = __shfl_sync(0xffffffffu, i10, i);
            int a11 = __shfl_sync(0xffffffffu, i11, i);
            uint32_t wA = __ldg(zt + a00 + lane);
            uint32_t wB = __ldg(zt + a01 + lane);
            uint32_t wC = __ldg(zt + a10 + lane);
            uint32_t wD = __ldg(zt + a11 + lane);
            float2 A = __half22float2(*reinterpret_cast<__half2*>(&wA));
            float2 B = __half22float2(*reinterpret_cast<__half2*>(&wB));
            float2 C = __half22float2(*reinterpret_cast<__half2*>(&wC));
            float2 D = __half22float2(*reinterpret_cast<__half2*>(&wD));
            float v0 = wwa * A.x + wwb * B.x + wwc * C.x + wwd * D.x;
            float v1 = wwa * A.y + wwb * B.y + wwc * C.y + wwd * D.y;
            *(uint32_t*)(smem + rowBase + i * SA_STRIDE + lane * 4) = packh2(v0, v1);
        }

        float f0 = __ldg(fourierB + 2 * lane)     * 2.0943951023931953f;
        float f1 = __ldg(fourierB + 2 * lane + 1) * 2.0943951023931953f;
        #pragma unroll 4
        for (int i = 0; i < 16; i++) {
            float t = __shfl_sync(0xffffffffu, ct, i);
            float s0, c0, s1, c1;
            fsincos(f0 * t, s0, c0);
            fsincos(f1 * t, s1, c1);
            *(uint32_t*)(smem + rowBase + i * SA_STRIDE + 128 + lane * 4) = packh2(s0, s1);
            *(uint32_t*)(smem + rowBase + i * SA_STRIDE + 256 + lane * 4) = packh2(c0, c1);
        }

        #pragma unroll 4
        for (int i = 0; i < 16; i++) {
            float xcx = __shfl_sync(0xffffffffu, cx, i);
            float xcy = __shfl_sync(0xffffffffu, cy, i);
            if (lane < 12) {
                uint32_t w = 0;
                if (lane == 0)      w = packh2(xcx, xcy);
                else if (lane == 1) w = packh2(1.f, 0.f);
                *(uint32_t*)(smem + rowBase + i * SA_STRIDE + 384 + lane * 4) = w;
            }
        }
    }
    __syncthreads();   // sb2/sb3 ready

    // ldmatrix A address for this warp's 16 rows
    const uint32_t aAddr = sb + SM_A + (uint32_t)(warp * 16 + (lane & 15)) * SA_STRIDE + (lane >> 4) * 16;

    float d[16][4];

    // ================= layer 1 (A from smem, hi only) =================
    {
        const uint4* wf = g_wfrag4 + WF_L1 + lane;
        uint32_t Ah[4];
        ldsm4(Ah, aAddr);
        mma_group8_u4_z(d, Ah, wf, 0);
        mma_group8_u4_z(d, Ah, wf, 4);
        #pragma unroll 1
        for (int kt = 1; kt < L1_KT; kt++) {
            ldsm4(Ah, aAddr + kt * 32);
            const uint4* p = wf + kt * 256;
            mma_group8_u4(d, Ah, p, 0);
            mma_group8_u4(d, Ah, p, 4);
        }
    }

    // epilogue 1 -> A2 via packed hardware tanh (bias folded into W1)
    uint32_t A2h[8][4];
    #pragma unroll
    for (int kt = 0; kt < 8; kt++)
        #pragma unroll
        for (int j = 0; j < 4; j++) {
            int srcnt = 2 * kt + (j >> 1);
            int c = (j & 1) * 2;
            A2h[kt][j] = tanh_h2(packh2(d[srcnt][c], d[srcnt][c + 1]));
        }

    // ================= layer 2 (A in registers) =================
    {
        const uint4* wf = g_wfrag4 + WF_L2 + lane;
        mma_group8_u4_z(d, A2h[0], wf, 0);
        mma_group8_u4_z(d, A2h[0], wf, 4);
        #pragma unroll 1
        for (int kt = 1; kt < L23_KT; kt++) {
            const uint4* p = wf + kt * 256;
            mma_group8_u4(d, A2h[kt], p, 0);
            mma_group8_u4(d, A2h[kt], p, 4);
        }
    }

    // epilogue 2: +b2 then packed tanh -> A3 (reuse A2h)
    #pragma unroll
    for (int kt = 0; kt < 8; kt++)
        #pragma unroll
        for (int j = 0; j < 4; j++) {
            int srcnt = 2 * kt + (j >> 1);
            int c = (j & 1) * 2;
            int col = 8 * srcnt + (lane & 3) * 2;
            float2 bb = *(float2*)(sb2 + col);
            A2h[kt][j] = tanh_h2(packh2(d[srcnt][c] + bb.x, d[srcnt][c + 1] + bb.y));
        }

    // ================= layer 3 (A in registers) =================
    {
        const uint4* wf = g_wfrag4 + WF_L3 + lane;
        mma_group8_u4_z(d, A2h[0], wf, 0);
        mma_group8_u4_z(d, A2h[0], wf, 4);
        #pragma unroll 1
        for (int kt = 1; kt < L23_KT; kt++) {
            const uint4* p = wf + kt * 256;
            mma_group8_u4(d, A2h[kt], p, 0);
            mma_group8_u4(d, A2h[kt], p, 4);
        }
    }

    // epilogue 3: +b3 then packed tanh -> A4 (reuse A2h)
    #pragma unroll
    for (int kt = 0; kt < 8; kt++)
        #pragma unroll
        for (int j = 0; j < 4; j++) {
            int srcnt = 2 * kt + (j >> 1);
            int c = (j & 1) * 2;
            int col = 8 * srcnt + (lane & 3) * 2;
            float2 bb = *(float2*)(sb3 + col);
            A2h[kt][j] = tanh_h2(packh2(d[srcnt][c] + bb.x, d[srcnt][c + 1] + bb.y));
        }

    // ================= heads as MMA (N=8; W hi+lo, A hi) =================
    {
        float dh[4];
        const uint4* hf = g_hfrag + lane;
        {
            uint4 HW = __ldg(hf);
            mma_f16_z(dh, A2h[0], HW.x, HW.y);
            mma_f16(dh, A2h[0], HW.z, HW.w);
        }
        #pragma unroll
        for (int kt = 1; kt < 8; kt++) {
            uint4 HW = __ldg(hf + kt * 32);
            mma_f16(dh, A2h[kt], HW.x, HW.y);   // AhWh
            mma_f16(dh, A2h[kt], HW.z, HW.w);   // AhWl
        }
        int c0 = (lane & 3) * 2;
        int r0 = blockIdx.x * PTS + warp * 16 + (lane >> 2);
        float hb0 = g_hb[c0], hb1 = g_hb[c0 + 1];
        float a0 = dh[0] + hb0, a1 = dh[1] + hb1;
        float a2 = dh[2] + hb0, a3 = dh[3] + hb1;
        if (c0 == 6) {   // col 7 = softplus(.) + MIN_STD
            a1 = fmaxf(a1, 0.f) + log1pf(expf(-fabsf(a1))) + 0.01f;
            a3 = fmaxf(a3, 0.f) + log1pf(expf(-fabsf(a3))) + 0.01f;
        }
        *(float2*)(out + r0 * 8 + c0)       = make_float2(a0, a1);
        *(float2*)(out + (r0 + 8) * 8 + c0) = make_float2(a2, a3);
    }
}

// ---------------- host launch ----------------
extern "C" void kernel_launch(void* const* d_in, const int* in_sizes, int n_in,
                              void* d_out, int out_size) {
    const float* coords   = (const float*)d_in[0];
    const float* z_grid   = (const float*)d_in[1];
    const float* fourierB = (const float*)d_in[2];
    const float* W1   = (const float*)d_in[3];
    const float* b1   = (const float*)d_in[4];
    const float* W2   = (const float*)d_in[5];
    const float* b2   = (const float*)d_in[6];
    const float* W3   = (const float*)d_in[7];
    const float* b3   = (const float*)d_in[8];
    const float* Wvel = (const float*)d_in[9];
    const float* bvel = (const float*)d_in[10];
    const float* Wfh  = (const float*)d_in[11];
    const float* bfh  = (const float*)d_in[12];
    const float* Wph  = (const float*)d_in[13];
    const float* bph  = (const float*)d_in[14];
    const float* Wmu  = (const float*)d_in[15];
    const float* bmu  = (const float*)d_in[16];
    const float* Wstd = (const float*)d_in[17];
    const float* bstd = (const float*)d_in[18];
    float* out = (float*)d_out;

    static bool attr_set = false;
    if (!attr_set) {
        cudaFuncSetAttribute(pinn_main, cudaFuncAttributeMaxDynamicSharedMemorySize, SM_TOTAL);
        attr_set = true;
    }

    prologue_kernel<<<PRO_TOTAL, 256>>>(
        z_grid, W1, b1, W2, W3,
        Wvel, bvel, Wfh, bfh, Wph, bph, Wmu, bmu, Wstd, bstd);
    pinn_main<<<NBLK, TPB, SM_TOTAL>>>(coords, fourierB, b2, b3, out);
}